// round 6
// baseline (speedup 1.0000x reference)
#include <cuda_runtime.h>
#include <cuda_bf16.h>

// Problem constants
#define BB   2
#define SS   2048
#define DD   1024
#define HH   16
#define DHH  64
#define MM   (BB*SS)      // 4096

// -------- scratch (device globals; allocation-free) --------
__device__ float g_q[MM * DD];
__device__ float g_k[MM * DD];
__device__ float g_v[MM * DD];
__device__ float g_att[MM * DD];

// ============================================================
// SGEMM NT:  C[m,n] = sum_k A[m,k] * B[n,k]
// Block tile 128x128x16, 256 threads, 8x8 micro-tile.
// ============================================================
#define TM 128
#define TN 128
#define TK 16

__device__ __forceinline__ void gemm_nt_body(
    const float* __restrict__ A,   // [M,K] row-major
    const float* __restrict__ Bm,  // [N,K] row-major (weights)
    float* __restrict__ C,         // [M,N] row-major
    int M, int N, int K)
{
    __shared__ float As[TK][TM];
    __shared__ float Bs[TK][TN];

    const int tid = threadIdx.x;
    const int tx  = tid & 15;     // 0..15
    const int ty  = tid >> 4;     // 0..15
    const int bm  = blockIdx.y * TM;
    const int bn  = blockIdx.x * TN;

    const int lr = tid >> 2;           // 0..63
    const int lk = (tid & 3) * 4;      // 0,4,8,12

    float c[8][8];
#pragma unroll
    for (int i = 0; i < 8; i++)
#pragma unroll
        for (int j = 0; j < 8; j++) c[i][j] = 0.f;

    for (int k0 = 0; k0 < K; k0 += TK) {
#pragma unroll
        for (int i = 0; i < 2; i++) {
            int row = lr + i * 64;
            float4 v = *(const float4*)&A[(size_t)(bm + row) * K + k0 + lk];
            As[lk + 0][row] = v.x; As[lk + 1][row] = v.y;
            As[lk + 2][row] = v.z; As[lk + 3][row] = v.w;
        }
#pragma unroll
        for (int i = 0; i < 2; i++) {
            int row = lr + i * 64;
            float4 v = *(const float4*)&Bm[(size_t)(bn + row) * K + k0 + lk];
            Bs[lk + 0][row] = v.x; Bs[lk + 1][row] = v.y;
            Bs[lk + 2][row] = v.z; Bs[lk + 3][row] = v.w;
        }
        __syncthreads();

#pragma unroll
        for (int kk = 0; kk < TK; kk++) {
            float4 a0 = *(const float4*)&As[kk][ty * 4];
            float4 a1 = *(const float4*)&As[kk][ty * 4 + 64];
            float4 b0 = *(const float4*)&Bs[kk][tx * 4];
            float4 b1 = *(const float4*)&Bs[kk][tx * 4 + 64];
            float av[8] = {a0.x, a0.y, a0.z, a0.w, a1.x, a1.y, a1.z, a1.w};
            float bv[8] = {b0.x, b0.y, b0.z, b0.w, b1.x, b1.y, b1.z, b1.w};
#pragma unroll
            for (int i = 0; i < 8; i++)
#pragma unroll
                for (int j = 0; j < 8; j++)
                    c[i][j] = fmaf(av[i], bv[j], c[i][j]);
        }
        __syncthreads();
    }

#pragma unroll
    for (int i = 0; i < 8; i++) {
        int row = bm + ((i < 4) ? (ty * 4 + i) : (64 + ty * 4 + (i - 4)));
#pragma unroll
        for (int jh = 0; jh < 2; jh++) {
            int col = bn + tx * 4 + jh * 64;
            float4 v = make_float4(c[i][jh * 4 + 0], c[i][jh * 4 + 1],
                                   c[i][jh * 4 + 2], c[i][jh * 4 + 3]);
            *(float4*)&C[(size_t)row * N + col] = v;
        }
    }
}

__global__ __launch_bounds__(256) void qkv_gemm_kernel(
    const float* __restrict__ x,
    const float* __restrict__ Wq,
    const float* __restrict__ Wk,
    const float* __restrict__ Wv)
{
    const float* Bm;
    float* C;
    if (blockIdx.z == 0)      { Bm = Wq; C = g_q; }
    else if (blockIdx.z == 1) { Bm = Wk; C = g_k; }
    else                      { Bm = Wv; C = g_v; }
    gemm_nt_body(x, Bm, C, MM, DD, DD);
}

__global__ __launch_bounds__(256) void out_gemm_kernel(
    const float* __restrict__ Wo, float* __restrict__ out)
{
    gemm_nt_body(g_att, Wo, out, MM, DD, DD);
}

// ============================================================
// Flash attention (fp32, causal).
// One CTA per (q-tile of 64 rows, b*H+h). 256 threads.
// smem: Qt[d][r] 16KB + KP (Kt[d][j] then Pt[j][r]) 16KB + Vs[j][d] 16KB = 48KB
// Thread (ty,tx) owns a 4x4 micro-tile: rows ty*4.., cols tx*4..
// ============================================================
__global__ __launch_bounds__(256) void flash_attn_kernel()
{
    __shared__ float Qt[64][64];
    __shared__ float KP[64][64];
    __shared__ float Vs[64][64];

    const int tid = threadIdx.x;
    const int tx  = tid & 15;
    const int ty  = tid >> 4;
    const int qt  = blockIdx.x;           // 0..31
    const int bh  = blockIdx.y;           // 0..31
    const int b   = bh >> 4;
    const int h   = bh & 15;

    const float* Qb = g_q   + (size_t)b * SS * DD + h * DHH;
    const float* Kb = g_k   + (size_t)b * SS * DD + h * DHH;
    const float* Vb = g_v   + (size_t)b * SS * DD + h * DHH;
    float*       Ob = g_att + (size_t)b * SS * DD + h * DHH;

    const float scale = 0.125f;  // 1/sqrt(64)

    // Load Q tile (pre-scaled), transposed: Qt[d][r]
#pragma unroll
    for (int it = 0; it < 4; it++) {
        int r = (tid >> 4) + it * 16;
        int d = (tid & 15) * 4;
        float4 v = *(const float4*)&Qb[(size_t)(qt * 64 + r) * DD + d];
        Qt[d + 0][r] = v.x * scale; Qt[d + 1][r] = v.y * scale;
        Qt[d + 2][r] = v.z * scale; Qt[d + 3][r] = v.w * scale;
    }

    float o[4][4];
    float m_i[4], l_i[4];
#pragma unroll
    for (int i = 0; i < 4; i++) {
        m_i[i] = -1e30f; l_i[i] = 0.f;
#pragma unroll
        for (int j = 0; j < 4; j++) o[i][j] = 0.f;
    }

    for (int kt = 0; kt <= qt; kt++) {
        __syncthreads();  // prior-iter reads of KP/Vs done (also orders Qt stores on iter 0)
        // Load K (transposed) and V tiles
#pragma unroll
        for (int it = 0; it < 4; it++) {
            int r = (tid >> 4) + it * 16;
            int d = (tid & 15) * 4;
            float4 kv = *(const float4*)&Kb[(size_t)(kt * 64 + r) * DD + d];
            KP[d + 0][r] = kv.x; KP[d + 1][r] = kv.y;
            KP[d + 2][r] = kv.z; KP[d + 3][r] = kv.w;
            float4 vv = *(const float4*)&Vb[(size_t)(kt * 64 + r) * DD + d];
            *(float4*)&Vs[r][d] = vv;
        }
        __syncthreads();

        // Scores: s[r][j] = Q[r]·K[j] (Q pre-scaled)
        float s[4][4];
#pragma unroll
        for (int i = 0; i < 4; i++)
#pragma unroll
            for (int j = 0; j < 4; j++) s[i][j] = 0.f;

#pragma unroll
        for (int kk = 0; kk < 64; kk++) {
            float4 a  = *(const float4*)&Qt[kk][ty * 4];
            float4 bq = *(const float4*)&KP[kk][tx * 4];
            float av[4] = {a.x, a.y, a.z, a.w};
            float bv[4] = {bq.x, bq.y, bq.z, bq.w};
#pragma unroll
            for (int i = 0; i < 4; i++)
#pragma unroll
                for (int j = 0; j < 4; j++)
                    s[i][j] = fmaf(av[i], bv[j], s[i][j]);
        }

        // Causal mask on diagonal tile
        if (kt == qt) {
#pragma unroll
            for (int i = 0; i < 4; i++) {
                int q = ty * 4 + i;
#pragma unroll
                for (int j = 0; j < 4; j++) {
                    if (tx * 4 + j > q) s[i][j] = -1e30f;
                }
            }
        }

        // Online softmax (row groups are 16 consecutive lanes; xor 8,4,2,1 stays in group)
        float p[4][4];
#pragma unroll
        for (int i = 0; i < 4; i++) {
            float rm = fmaxf(fmaxf(s[i][0], s[i][1]), fmaxf(s[i][2], s[i][3]));
#pragma unroll
            for (int off = 8; off > 0; off >>= 1)
                rm = fmaxf(rm, __shfl_xor_sync(0xffffffffu, rm, off));
            float mn  = fmaxf(m_i[i], rm);
            float fac = __expf(m_i[i] - mn);
            float rs  = 0.f;
#pragma unroll
            for (int j = 0; j < 4; j++) {
                p[i][j] = __expf(s[i][j] - mn);
                rs += p[i][j];
            }
#pragma unroll
            for (int off = 8; off > 0; off >>= 1)
                rs += __shfl_xor_sync(0xffffffffu, rs, off);
            l_i[i] = l_i[i] * fac + rs;
            m_i[i] = mn;
#pragma unroll
            for (int j = 0; j < 4; j++) o[i][j] *= fac;
        }

        __syncthreads();  // all threads done reading KP as K
        // Store P transposed into KP: Pt[j][r]
#pragma unroll
        for (int i = 0; i < 4; i++)
#pragma unroll
            for (int j = 0; j < 4; j++)
                KP[tx * 4 + j][ty * 4 + i] = p[i][j];
        __syncthreads();

        // O += P @ V
#pragma unroll
        for (int j = 0; j < 64; j++) {
            float4 a  = *(const float4*)&KP[j][ty * 4];   // P[r][j] for 4 rows
            float4 bb = *(const float4*)&Vs[j][tx * 4];   // V[j][d] for 4 d's
            float av[4] = {a.x, a.y, a.z, a.w};
            float bv[4] = {bb.x, bb.y, bb.z, bb.w};
#pragma unroll
            for (int i = 0; i < 4; i++)
#pragma unroll
                for (int jj = 0; jj < 4; jj++)
                    o[i][jj] = fmaf(av[i], bv[jj], o[i][jj]);
        }
    }

    // Finalize: divide by l, write to g_att in [B,S,H*Dh] layout
#pragma unroll
    for (int i = 0; i < 4; i++) {
        float inv = 1.0f / l_i[i];
        int row = qt * 64 + ty * 4 + i;
        float4 v = make_float4(o[i][0] * inv, o[i][1] * inv,
                               o[i][2] * inv, o[i][3] * inv);
        *(float4*)&Ob[(size_t)row * DD + tx * 4] = v;
    }
}

// ============================================================
extern "C" void kernel_launch(void* const* d_in, const int* in_sizes, int n_in,
                              void* d_out, int out_size)
{
    const float* x  = (const float*)d_in[0];
    const float* Wq = (const float*)d_in[1];
    const float* Wk = (const float*)d_in[2];
    const float* Wv = (const float*)d_in[3];
    const float* Wo = (const float*)d_in[4];
    float* out = (float*)d_out;

    dim3 gproj(DD / TN, MM / TM, 3);   // 8 x 32 x 3
    qkv_gemm_kernel<<<gproj, 256>>>(x, Wq, Wk, Wv);

    dim3 gattn(SS / 64, BB * HH);      // 32 x 32
    flash_attn_kernel<<<gattn, 256>>>();

    dim3 gout(DD / TN, MM / TM);       // 8 x 32
    out_gemm_kernel<<<gout, 256>>>(Wo, out);
}

// round 7
// speedup vs baseline: 1.0675x; 1.0675x over previous
#include <cuda_runtime.h>
#include <cuda_bf16.h>
#include <mma.h>

using namespace nvcuda;
namespace wm = nvcuda::wmma;
using tf32_t = wm::precision::tf32;

// Problem constants
#define BB   2
#define SS   2048
#define DD   1024
#define HH   16
#define DHH  64
#define MM   (BB*SS)      // 4096

// -------- scratch (device globals; allocation-free) --------
__device__ float g_q[MM * DD];
__device__ float g_k[MM * DD];
__device__ float g_v[MM * DD];
__device__ float g_att[MM * DD];

// ============================================================
// TF32 WMMA GEMM NT:  C[m,n] = sum_k A[m,k] * B[n,k]
// Block 128x128, k-tile 32, 256 threads (8 warps).
// Warp grid 4(m) x 2(n); warp tile 32x64 = 2x4 wmma 16x16 tiles.
// ============================================================
#define PPAD 40   // smem pitch (floats), multiple of 8

__device__ __forceinline__ void gemm_nt_tf32_body(
    const float* __restrict__ A,   // [M,K] row-major
    const float* __restrict__ Bm,  // [N,K] row-major (weights)
    float* __restrict__ C,         // [M,N] row-major
    int N, int K)
{
    __shared__ float As[128][PPAD];
    __shared__ float Bs[128][PPAD];

    const int tid  = threadIdx.x;
    const int warp = tid >> 5;
    const int wmi  = warp >> 1;   // 0..3  (m)
    const int wni  = warp & 1;    // 0..1  (n)
    const int bm   = blockIdx.y * 128;
    const int bn   = blockIdx.x * 128;

    wm::fragment<wm::accumulator, 16, 16, 8, float> acc[2][4];
#pragma unroll
    for (int i = 0; i < 2; i++)
#pragma unroll
        for (int j = 0; j < 4; j++) wm::fill_fragment(acc[i][j], 0.f);

    for (int k0 = 0; k0 < K; k0 += 32) {
        // load + convert tiles: 128 rows x 32 cols = 1024 float4s
#pragma unroll
        for (int p = 0; p < 4; p++) {
            int fidx = tid + p * 256;
            int row  = fidx >> 3;
            int col  = (fidx & 7) * 4;
            float4 va = *(const float4*)&A[(size_t)(bm + row) * K + k0 + col];
            va.x = wm::__float_to_tf32(va.x); va.y = wm::__float_to_tf32(va.y);
            va.z = wm::__float_to_tf32(va.z); va.w = wm::__float_to_tf32(va.w);
            *(float4*)&As[row][col] = va;
            float4 vb = *(const float4*)&Bm[(size_t)(bn + row) * K + k0 + col];
            vb.x = wm::__float_to_tf32(vb.x); vb.y = wm::__float_to_tf32(vb.y);
            vb.z = wm::__float_to_tf32(vb.z); vb.w = wm::__float_to_tf32(vb.w);
            *(float4*)&Bs[row][col] = vb;
        }
        __syncthreads();

#pragma unroll
        for (int ks = 0; ks < 4; ks++) {
            wm::fragment<wm::matrix_a, 16, 16, 8, tf32_t, wm::row_major> af[2];
            wm::fragment<wm::matrix_b, 16, 16, 8, tf32_t, wm::col_major> bf[4];
#pragma unroll
            for (int i = 0; i < 2; i++)
                wm::load_matrix_sync(af[i], &As[wmi * 32 + i * 16][ks * 8], PPAD);
#pragma unroll
            for (int j = 0; j < 4; j++)
                wm::load_matrix_sync(bf[j], &Bs[wni * 64 + j * 16][ks * 8], PPAD);
#pragma unroll
            for (int i = 0; i < 2; i++)
#pragma unroll
                for (int j = 0; j < 4; j++)
                    wm::mma_sync(acc[i][j], af[i], bf[j], acc[i][j]);
        }
        __syncthreads();
    }

#pragma unroll
    for (int i = 0; i < 2; i++)
#pragma unroll
        for (int j = 0; j < 4; j++) {
            int row = bm + wmi * 32 + i * 16;
            int col = bn + wni * 64 + j * 16;
            wm::store_matrix_sync(&C[(size_t)row * N + col], acc[i][j], N,
                                  wm::mem_row_major);
        }
}

__global__ __launch_bounds__(256) void qkv_gemm_kernel(
    const float* __restrict__ x,
    const float* __restrict__ Wq,
    const float* __restrict__ Wk,
    const float* __restrict__ Wv)
{
    const float* Bm;
    float* C;
    if (blockIdx.z == 0)      { Bm = Wq; C = g_q; }
    else if (blockIdx.z == 1) { Bm = Wk; C = g_k; }
    else                      { Bm = Wv; C = g_v; }
    gemm_nt_tf32_body(x, Bm, C, DD, DD);
}

__global__ __launch_bounds__(256) void out_gemm_kernel(
    const float* __restrict__ Wo, float* __restrict__ out)
{
    gemm_nt_tf32_body(g_att, Wo, out, DD, DD);
}

// ============================================================
// Flash attention, tf32 tensor cores, causal.
// One CTA per (64-row q-tile, b*H+h). 256 threads, 8 warps.
// Dynamic smem: Qs, Ks, Vs, SP, Os  each [64][72] floats = 90KB.
// Warp grid for both mmas: 4(m=16 rows) x 2(n=32 cols).
// ============================================================
#define APAD 72

__global__ __launch_bounds__(256) void flash_attn_kernel()
{
    extern __shared__ float smem[];
    float (*Qs)[APAD] = (float(*)[APAD])(smem);
    float (*Ks)[APAD] = (float(*)[APAD])(smem + 64 * APAD);
    float (*Vs)[APAD] = (float(*)[APAD])(smem + 2 * 64 * APAD);
    float (*SP)[APAD] = (float(*)[APAD])(smem + 3 * 64 * APAD);
    float (*Os)[APAD] = (float(*)[APAD])(smem + 4 * 64 * APAD);

    const int tid  = threadIdx.x;
    const int warp = tid >> 5;
    const int wmi  = warp >> 1;   // 0..3
    const int wni  = warp & 1;    // 0..1
    const int qt   = blockIdx.x;  // 0..31
    const int bh   = blockIdx.y;  // 0..31
    const int b    = bh >> 4;
    const int h    = bh & 15;

    const float* Qb = g_q   + (size_t)b * SS * DD + h * DHH;
    const float* Kb = g_k   + (size_t)b * SS * DD + h * DHH;
    const float* Vb = g_v   + (size_t)b * SS * DD + h * DHH;
    float*       Ob = g_att + (size_t)b * SS * DD + h * DHH;

    const float scale = 0.125f;  // 1/sqrt(64)

    // Load Q (prescaled, tf32) and zero Os: 64x64 -> 256 float4s
#pragma unroll
    for (int p = 0; p < 4; p++) {
        int fidx = tid + p * 256;         // 0..1023
        int row  = fidx >> 4;
        int col  = (fidx & 15) * 4;
        float4 v = *(const float4*)&Qb[(size_t)(qt * 64 + row) * DD + col];
        v.x = wm::__float_to_tf32(v.x * scale);
        v.y = wm::__float_to_tf32(v.y * scale);
        v.z = wm::__float_to_tf32(v.z * scale);
        v.w = wm::__float_to_tf32(v.w * scale);
        *(float4*)&Qs[row][col] = v;
        *(float4*)&Os[row][col] = make_float4(0.f, 0.f, 0.f, 0.f);
    }

    // softmax row ownership: 4 lanes per row
    const int srow = tid >> 2;            // 0..63
    const int scol = (tid & 3) * 16;      // 0,16,32,48
    float m_i = -1e30f, l_i = 0.f;

    for (int kt = 0; kt <= qt; kt++) {
        __syncthreads();  // prior iter done with Ks/Vs/SP/Os
        // Load K (tf32) and V (tf32)
#pragma unroll
        for (int p = 0; p < 4; p++) {
            int fidx = tid + p * 256;
            int row  = fidx >> 4;
            int col  = (fidx & 15) * 4;
            float4 kv = *(const float4*)&Kb[(size_t)(kt * 64 + row) * DD + col];
            kv.x = wm::__float_to_tf32(kv.x); kv.y = wm::__float_to_tf32(kv.y);
            kv.z = wm::__float_to_tf32(kv.z); kv.w = wm::__float_to_tf32(kv.w);
            *(float4*)&Ks[row][col] = kv;
            float4 vv = *(const float4*)&Vb[(size_t)(kt * 64 + row) * DD + col];
            vv.x = wm::__float_to_tf32(vv.x); vv.y = wm::__float_to_tf32(vv.y);
            vv.z = wm::__float_to_tf32(vv.z); vv.w = wm::__float_to_tf32(vv.w);
            *(float4*)&Vs[row][col] = vv;
        }
        __syncthreads();

        // S = Q @ K^T  (warp tile 16x32)
        {
            wm::fragment<wm::accumulator, 16, 16, 8, float> sacc[2];
            wm::fill_fragment(sacc[0], 0.f);
            wm::fill_fragment(sacc[1], 0.f);
#pragma unroll
            for (int ks = 0; ks < 8; ks++) {
                wm::fragment<wm::matrix_a, 16, 16, 8, tf32_t, wm::row_major> af;
                wm::load_matrix_sync(af, &Qs[wmi * 16][ks * 8], APAD);
#pragma unroll
                for (int j = 0; j < 2; j++) {
                    wm::fragment<wm::matrix_b, 16, 16, 8, tf32_t, wm::col_major> bf;
                    wm::load_matrix_sync(bf, &Ks[wni * 32 + j * 16][ks * 8], APAD);
                    wm::mma_sync(sacc[j], af, bf, sacc[j]);
                }
            }
#pragma unroll
            for (int j = 0; j < 2; j++)
                wm::store_matrix_sync(&SP[wmi * 16][wni * 32 + j * 16], sacc[j],
                                      APAD, wm::mem_row_major);
        }
        __syncthreads();

        // Online softmax: 4 lanes per row, 16 cols each
        {
            float s[16];
#pragma unroll
            for (int j = 0; j < 16; j++) s[j] = SP[srow][scol + j];
            if (kt == qt) {
#pragma unroll
                for (int j = 0; j < 16; j++)
                    if (scol + j > srow) s[j] = -1e30f;
            }
            float rm = s[0];
#pragma unroll
            for (int j = 1; j < 16; j++) rm = fmaxf(rm, s[j]);
            rm = fmaxf(rm, __shfl_xor_sync(0xffffffffu, rm, 1));
            rm = fmaxf(rm, __shfl_xor_sync(0xffffffffu, rm, 2));
            float mn  = fmaxf(m_i, rm);
            float fac = __expf(m_i - mn);
            float rs  = 0.f;
#pragma unroll
            for (int j = 0; j < 16; j++) {
                s[j] = __expf(s[j] - mn);
                rs += s[j];
            }
            rs += __shfl_xor_sync(0xffffffffu, rs, 1);
            rs += __shfl_xor_sync(0xffffffffu, rs, 2);
            l_i = l_i * fac + rs;
            m_i = mn;
            // rescale O rows and write P (tf32) in place of S
#pragma unroll
            for (int j = 0; j < 16; j += 4) {
                float4 ov = *(float4*)&Os[srow][scol + j];
                ov.x *= fac; ov.y *= fac; ov.z *= fac; ov.w *= fac;
                *(float4*)&Os[srow][scol + j] = ov;
                float4 pv = make_float4(wm::__float_to_tf32(s[j + 0]),
                                        wm::__float_to_tf32(s[j + 1]),
                                        wm::__float_to_tf32(s[j + 2]),
                                        wm::__float_to_tf32(s[j + 3]));
                *(float4*)&SP[srow][scol + j] = pv;
            }
        }
        __syncthreads();

        // O += P @ V  (warp tile 16x32, accumulate via Os)
        {
            wm::fragment<wm::accumulator, 16, 16, 8, float> oacc[2];
#pragma unroll
            for (int j = 0; j < 2; j++)
                wm::load_matrix_sync(oacc[j], &Os[wmi * 16][wni * 32 + j * 16],
                                     APAD, wm::mem_row_major);
#pragma unroll
            for (int ks = 0; ks < 8; ks++) {
                wm::fragment<wm::matrix_a, 16, 16, 8, tf32_t, wm::row_major> af;
                wm::load_matrix_sync(af, &SP[wmi * 16][ks * 8], APAD);
#pragma unroll
                for (int j = 0; j < 2; j++) {
                    wm::fragment<wm::matrix_b, 16, 16, 8, tf32_t, wm::row_major> bf;
                    wm::load_matrix_sync(bf, &Vs[ks * 8][wni * 32 + j * 16], APAD);
                    wm::mma_sync(oacc[j], af, bf, oacc[j]);
                }
            }
#pragma unroll
            for (int j = 0; j < 2; j++)
                wm::store_matrix_sync(&Os[wmi * 16][wni * 32 + j * 16], oacc[j],
                                      APAD, wm::mem_row_major);
        }
    }

    __syncthreads();
    // Finalize: each row-owning lane writes its 16-col segment
    {
        float inv = 1.0f / l_i;
        int grow = qt * 64 + srow;
#pragma unroll
        for (int j = 0; j < 16; j += 4) {
            float4 ov = *(float4*)&Os[srow][scol + j];
            ov.x *= inv; ov.y *= inv; ov.z *= inv; ov.w *= inv;
            *(float4*)&Ob[(size_t)grow * DD + scol + j] = ov;
        }
    }
}

// ============================================================
extern "C" void kernel_launch(void* const* d_in, const int* in_sizes, int n_in,
                              void* d_out, int out_size)
{
    const float* x  = (const float*)d_in[0];
    const float* Wq = (const float*)d_in[1];
    const float* Wk = (const float*)d_in[2];
    const float* Wv = (const float*)d_in[3];
    const float* Wo = (const float*)d_in[4];
    float* out = (float*)d_out;

    const int attn_smem = 5 * 64 * APAD * sizeof(float);  // 92160 B
    cudaFuncSetAttribute(flash_attn_kernel,
                         cudaFuncAttributeMaxDynamicSharedMemorySize, attn_smem);

    dim3 gproj(DD / 128, MM / 128, 3);   // 8 x 32 x 3
    qkv_gemm_kernel<<<gproj, 256>>>(x, Wq, Wk, Wv);

    dim3 gattn(SS / 64, BB * HH);        // 32 x 32
    flash_attn_kernel<<<gattn, 256, attn_smem>>>();

    dim3 gout(DD / 128, MM / 128);       // 8 x 32
    out_gemm_kernel<<<gout, 256>>>(Wo, out);
}

// round 9
// speedup vs baseline: 1.5985x; 1.4975x over previous
#include <cuda_runtime.h>
#include <cuda_bf16.h>
#include <mma.h>
#include <cstdint>

using namespace nvcuda;
namespace wm = nvcuda::wmma;
using tf32_t = wm::precision::tf32;

// Problem constants
#define BB   2
#define SS   2048
#define DD   1024
#define HH   16
#define DHH  64
#define MM   (BB*SS)      // 4096

// -------- scratch (device globals; allocation-free) --------
__device__ float g_q[MM * DD];     // tf32-rounded Q (BSD layout)
__device__ float g_k[MM * DD];
__device__ float g_v[MM * DD];
__device__ float g_att[MM * DD];   // tf32-rounded attention output
__device__ float g_xt[MM * DD];    // tf32-rounded x
__device__ float g_wq[DD * DD];    // tf32-rounded weights
__device__ float g_wk[DD * DD];
__device__ float g_wv[DD * DD];
__device__ float g_wo[DD * DD];

// ---------------- cp.async helpers ----------------
__device__ __forceinline__ uint32_t smem_u32(const void* p) {
    uint32_t a;
    asm("{ .reg .u64 t; cvta.to.shared.u64 t, %1; cvt.u32.u64 %0, t; }"
        : "=r"(a) : "l"(p));
    return a;
}
#define CP_ASYNC16(dst_u32, src_ptr) \
    asm volatile("cp.async.cg.shared.global [%0], [%1], 16;" \
                 :: "r"(dst_u32), "l"(src_ptr) : "memory")
#define CP_COMMIT() asm volatile("cp.async.commit_group;" ::: "memory")
#define CP_WAIT1()  asm volatile("cp.async.wait_group 1;" ::: "memory")
#define CP_WAIT0()  asm volatile("cp.async.wait_group 0;" ::: "memory")

extern __shared__ __align__(1024) float smemf[];

// ============================================================
// tf32 conversion kernel (grid-stride over float4)
// ============================================================
__global__ __launch_bounds__(256) void conv_tf32_kernel(
    const float* __restrict__ src, float* __restrict__ dst, int n4)
{
    int i = blockIdx.x * blockDim.x + threadIdx.x;
    if (i < n4) {
        float4 v = ((const float4*)src)[i];
        v.x = wm::__float_to_tf32(v.x); v.y = wm::__float_to_tf32(v.y);
        v.z = wm::__float_to_tf32(v.z); v.w = wm::__float_to_tf32(v.w);
        ((float4*)dst)[i] = v;
    }
}

// ============================================================
// TF32 WMMA GEMM NT with cp.async double buffering.
// C[m,n] = sum_k A[m,k] * B[n,k]; A,B pre-converted tf32.
// Block 128x128, k-tile 32, 256 threads, warp tile 32x64.
// ============================================================
#define PPAD 40                      // smem pitch (floats), mult of 8
#define G_STAGE_F (128 * PPAD)       // floats per operand per stage
#define G_NT (DD / 32)               // 32 k-tiles
#define G_SMEM_BYTES (2 * 2 * G_STAGE_F * 4)   // 81920

template <bool CONV_OUT>
__device__ __forceinline__ void gemm_body(
    const float* __restrict__ A, const float* __restrict__ Bm,
    float* __restrict__ C, int N, int K)
{
    const uint32_t sbase = smem_u32(smemf);
    const int tid  = threadIdx.x;
    const int warp = tid >> 5;
    const int wmi  = warp >> 1;
    const int wni  = warp & 1;
    const int bm   = blockIdx.y * 128;
    const int bn   = blockIdx.x * 128;

    // per-thread copy coords (4 chunks of float4 per operand tile)
    const int crow[4] = { (tid + 0)   >> 3, (tid + 256) >> 3,
                          (tid + 512) >> 3, (tid + 768) >> 3 };
    const int cc4 = tid & 7;

    auto issue = [&](int kt, int stage) {
        uint32_t as = sbase + (uint32_t)stage * 2 * G_STAGE_F * 4;
        uint32_t bs = as + G_STAGE_F * 4;
#pragma unroll
        for (int p = 0; p < 4; p++) {
            int row = crow[p];
            CP_ASYNC16(as + (uint32_t)(row * PPAD + cc4 * 4) * 4,
                       &A[(size_t)(bm + row) * K + kt * 32 + cc4 * 4]);
            CP_ASYNC16(bs + (uint32_t)(row * PPAD + cc4 * 4) * 4,
                       &Bm[(size_t)(bn + row) * K + kt * 32 + cc4 * 4]);
        }
    };

    wm::fragment<wm::accumulator, 16, 16, 8, float> acc[2][4];
#pragma unroll
    for (int i = 0; i < 2; i++)
#pragma unroll
        for (int j = 0; j < 4; j++) wm::fill_fragment(acc[i][j], 0.f);

    issue(0, 0); CP_COMMIT();
    issue(1, 1); CP_COMMIT();

    for (int kt = 0; kt < G_NT; kt++) {
        if (kt < G_NT - 2) { CP_WAIT1(); } else { CP_WAIT0(); }
        __syncthreads();

        const float* As = smemf + (kt & 1) * 2 * G_STAGE_F;
        const float* Bs = As + G_STAGE_F;
#pragma unroll
        for (int ks = 0; ks < 4; ks++) {
            wm::fragment<wm::matrix_a, 16, 16, 8, tf32_t, wm::row_major> af[2];
            wm::fragment<wm::matrix_b, 16, 16, 8, tf32_t, wm::col_major> bf[4];
#pragma unroll
            for (int i = 0; i < 2; i++)
                wm::load_matrix_sync(af[i], &As[(wmi * 32 + i * 16) * PPAD + ks * 8], PPAD);
#pragma unroll
            for (int j = 0; j < 4; j++)
                wm::load_matrix_sync(bf[j], &Bs[(wni * 64 + j * 16) * PPAD + ks * 8], PPAD);
#pragma unroll
            for (int i = 0; i < 2; i++)
#pragma unroll
                for (int j = 0; j < 4; j++)
                    wm::mma_sync(acc[i][j], af[i], bf[j], acc[i][j]);
        }
        __syncthreads();

        if (kt + 2 < G_NT) { issue(kt + 2, kt & 1); CP_COMMIT(); }
    }

#pragma unroll
    for (int i = 0; i < 2; i++)
#pragma unroll
        for (int j = 0; j < 4; j++) {
            if (CONV_OUT) {
#pragma unroll
                for (int t = 0; t < acc[i][j].num_elements; t++)
                    acc[i][j].x[t] = wm::__float_to_tf32(acc[i][j].x[t]);
            }
            int row = bm + wmi * 32 + i * 16;
            int col = bn + wni * 64 + j * 16;
            wm::store_matrix_sync(&C[(size_t)row * N + col], acc[i][j], N,
                                  wm::mem_row_major);
        }
}

__global__ __launch_bounds__(256) void qkv_gemm_kernel()
{
    const float* Bm;
    float* C;
    if (blockIdx.z == 0)      { Bm = g_wq; C = g_q; }
    else if (blockIdx.z == 1) { Bm = g_wk; C = g_k; }
    else                      { Bm = g_wv; C = g_v; }
    gemm_body<true>(g_xt, Bm, C, DD, DD);
}

__global__ __launch_bounds__(256) void out_gemm_kernel(float* __restrict__ out)
{
    gemm_body<false>(g_att, g_wo, out, DD, DD);
}

// ============================================================
// Flash attention, tf32 wmma, cp.async double-buffered K/V.
// One CTA per (64-row q-tile, b*H+h). 256 threads, 8 warps.
// smem: Qs, Ks0, Ks1, Vs0, Vs1, SP, Os each [64][72] = 129024 B.
// ============================================================
#define APAD 72
#define ATT_TILE_F (64 * APAD)
#define ATT_SMEM_BYTES (7 * ATT_TILE_F * 4)

__global__ __launch_bounds__(256) void flash_attn_kernel()
{
    float (*Qs)[APAD]    = (float(*)[APAD])(smemf);
    float (*Ks)[2][APAD] = nullptr;  // addressed manually below
    float* Kbuf[2] = { smemf + 1 * ATT_TILE_F, smemf + 2 * ATT_TILE_F };
    float* Vbuf[2] = { smemf + 3 * ATT_TILE_F, smemf + 4 * ATT_TILE_F };
    float (*SP)[APAD] = (float(*)[APAD])(smemf + 5 * ATT_TILE_F);
    float (*Os)[APAD] = (float(*)[APAD])(smemf + 6 * ATT_TILE_F);
    (void)Ks;

    const uint32_t sbase = smem_u32(smemf);
    const uint32_t kbase[2] = { sbase + 1 * ATT_TILE_F * 4, sbase + 2 * ATT_TILE_F * 4 };
    const uint32_t vbase[2] = { sbase + 3 * ATT_TILE_F * 4, sbase + 4 * ATT_TILE_F * 4 };

    const int tid  = threadIdx.x;
    const int warp = tid >> 5;
    const int wmi  = warp >> 1;
    const int wni  = warp & 1;
    const int qt   = blockIdx.x;
    const int bh   = blockIdx.y;
    const int b    = bh >> 4;
    const int h    = bh & 15;

    const float* Qb = g_q   + (size_t)b * SS * DD + h * DHH;
    const float* Kb = g_k   + (size_t)b * SS * DD + h * DHH;
    const float* Vb = g_v   + (size_t)b * SS * DD + h * DHH;
    float*       Ob = g_att + (size_t)b * SS * DD + h * DHH;

    // copy coords: 4 chunks/thread over 64x64 floats
    const int qrow[4] = { (tid + 0)   >> 4, (tid + 256) >> 4,
                          (tid + 512) >> 4, (tid + 768) >> 4 };
    const int qc4 = tid & 15;

    auto issue_kv = [&](int kt, int bsel) {
#pragma unroll
        for (int p = 0; p < 4; p++) {
            int row = qrow[p];
            uint32_t off = (uint32_t)(row * APAD + qc4 * 4) * 4;
            CP_ASYNC16(kbase[bsel] + off,
                       &Kb[(size_t)(kt * 64 + row) * DD + qc4 * 4]);
            CP_ASYNC16(vbase[bsel] + off,
                       &Vb[(size_t)(kt * 64 + row) * DD + qc4 * 4]);
        }
    };

    issue_kv(0, 0); CP_COMMIT();

    // Q (tf32 already; x0.125 is exact) + zero Os
#pragma unroll
    for (int p = 0; p < 4; p++) {
        int row = qrow[p];
        float4 v = *(const float4*)&Qb[(size_t)(qt * 64 + row) * DD + qc4 * 4];
        v.x *= 0.125f; v.y *= 0.125f; v.z *= 0.125f; v.w *= 0.125f;
        *(float4*)&Qs[row][qc4 * 4] = v;
        *(float4*)&Os[row][qc4 * 4] = make_float4(0.f, 0.f, 0.f, 0.f);
    }

    const int srow = tid >> 2;
    const int scol = (tid & 3) * 16;
    float m_i = -1e30f, l_i = 0.f;

    for (int kt = 0; kt <= qt; kt++) {
        const int bsel = kt & 1;
        if (kt < qt) { issue_kv(kt + 1, bsel ^ 1); CP_COMMIT(); CP_WAIT1(); }
        else         { CP_WAIT0(); }
        __syncthreads();

        const float (*Kt)[APAD] = (const float(*)[APAD])Kbuf[bsel];
        const float (*Vt)[APAD] = (const float(*)[APAD])Vbuf[bsel];

        // S = Q @ K^T
        {
            wm::fragment<wm::accumulator, 16, 16, 8, float> sacc[2];
            wm::fill_fragment(sacc[0], 0.f);
            wm::fill_fragment(sacc[1], 0.f);
#pragma unroll
            for (int ks = 0; ks < 8; ks++) {
                wm::fragment<wm::matrix_a, 16, 16, 8, tf32_t, wm::row_major> af;
                wm::load_matrix_sync(af, &Qs[wmi * 16][ks * 8], APAD);
#pragma unroll
                for (int j = 0; j < 2; j++) {
                    wm::fragment<wm::matrix_b, 16, 16, 8, tf32_t, wm::col_major> bf;
                    wm::load_matrix_sync(bf, &Kt[wni * 32 + j * 16][ks * 8], APAD);
                    wm::mma_sync(sacc[j], af, bf, sacc[j]);
                }
            }
#pragma unroll
            for (int j = 0; j < 2; j++)
                wm::store_matrix_sync(&SP[wmi * 16][wni * 32 + j * 16], sacc[j],
                                      APAD, wm::mem_row_major);
        }
        __syncthreads();

        // Online softmax: 4 lanes per row
        {
            float s[16];
#pragma unroll
            for (int j = 0; j < 16; j++) s[j] = SP[srow][scol + j];
            if (kt == qt) {
#pragma unroll
                for (int j = 0; j < 16; j++)
                    if (scol + j > srow) s[j] = -1e30f;
            }
            float rm = s[0];
#pragma unroll
            for (int j = 1; j < 16; j++) rm = fmaxf(rm, s[j]);
            rm = fmaxf(rm, __shfl_xor_sync(0xffffffffu, rm, 1));
            rm = fmaxf(rm, __shfl_xor_sync(0xffffffffu, rm, 2));
            float mn  = fmaxf(m_i, rm);
            float fac = __expf(m_i - mn);
            float rs  = 0.f;
#pragma unroll
            for (int j = 0; j < 16; j++) {
                s[j] = __expf(s[j] - mn);
                rs += s[j];
            }
            rs += __shfl_xor_sync(0xffffffffu, rs, 1);
            rs += __shfl_xor_sync(0xffffffffu, rs, 2);
            l_i = l_i * fac + rs;
            m_i = mn;
#pragma unroll
            for (int j = 0; j < 16; j += 4) {
                float4 ov = *(float4*)&Os[srow][scol + j];
                ov.x *= fac; ov.y *= fac; ov.z *= fac; ov.w *= fac;
                *(float4*)&Os[srow][scol + j] = ov;
                float4 pv = make_float4(wm::__float_to_tf32(s[j + 0]),
                                        wm::__float_to_tf32(s[j + 1]),
                                        wm::__float_to_tf32(s[j + 2]),
                                        wm::__float_to_tf32(s[j + 3]));
                *(float4*)&SP[srow][scol + j] = pv;
            }
        }
        __syncthreads();

        // O += P @ V
        {
            wm::fragment<wm::accumulator, 16, 16, 8, float> oacc[2];
#pragma unroll
            for (int j = 0; j < 2; j++)
                wm::load_matrix_sync(oacc[j], &Os[wmi * 16][wni * 32 + j * 16],
                                     APAD, wm::mem_row_major);
#pragma unroll
            for (int ks = 0; ks < 8; ks++) {
                wm::fragment<wm::matrix_a, 16, 16, 8, tf32_t, wm::row_major> af;
                wm::load_matrix_sync(af, &SP[wmi * 16][ks * 8], APAD);
#pragma unroll
                for (int j = 0; j < 2; j++) {
                    wm::fragment<wm::matrix_b, 16, 16, 8, tf32_t, wm::row_major> bf;
                    wm::load_matrix_sync(bf, &Vt[ks * 8][wni * 32 + j * 16], APAD);
                    wm::mma_sync(oacc[j], af, bf, oacc[j]);
                }
            }
#pragma unroll
            for (int j = 0; j < 2; j++)
                wm::store_matrix_sync(&Os[wmi * 16][wni * 32 + j * 16], oacc[j],
                                      APAD, wm::mem_row_major);
        }
        __syncthreads();   // also protects buffers for next iter's issue
    }

    // Finalize: divide by l, tf32-round (out_gemm consumes as tf32 A operand)
    {
        float inv = 1.0f / l_i;
        int grow = qt * 64 + srow;
#pragma unroll
        for (int j = 0; j < 16; j += 4) {
            float4 ov = *(float4*)&Os[srow][scol + j];
            ov.x = wm::__float_to_tf32(ov.x * inv);
            ov.y = wm::__float_to_tf32(ov.y * inv);
            ov.z = wm::__float_to_tf32(ov.z * inv);
            ov.w = wm::__float_to_tf32(ov.w * inv);
            *(float4*)&Ob[(size_t)grow * DD + scol + j] = ov;
        }
    }
}

// ============================================================
extern "C" void kernel_launch(void* const* d_in, const int* in_sizes, int n_in,
                              void* d_out, int out_size)
{
    const float* x  = (const float*)d_in[0];
    const float* Wq = (const float*)d_in[1];
    const float* Wk = (const float*)d_in[2];
    const float* Wv = (const float*)d_in[3];
    const float* Wo = (const float*)d_in[4];
    float* out = (float*)d_out;

    cudaFuncSetAttribute(qkv_gemm_kernel,
                         cudaFuncAttributeMaxDynamicSharedMemorySize, G_SMEM_BYTES);
    cudaFuncSetAttribute(out_gemm_kernel,
                         cudaFuncAttributeMaxDynamicSharedMemorySize, G_SMEM_BYTES);
    cudaFuncSetAttribute(flash_attn_kernel,
                         cudaFuncAttributeMaxDynamicSharedMemorySize, ATT_SMEM_BYTES);

    // resolve device-global addresses (host-side, graph-safe)
    float *p_xt, *p_wq, *p_wk, *p_wv, *p_wo;
    cudaGetSymbolAddress((void**)&p_xt, g_xt);
    cudaGetSymbolAddress((void**)&p_wq, g_wq);
    cudaGetSymbolAddress((void**)&p_wk, g_wk);
    cudaGetSymbolAddress((void**)&p_wv, g_wv);
    cudaGetSymbolAddress((void**)&p_wo, g_wo);

    // one-shot tf32 conversions
    conv_tf32_kernel<<<MM * DD / 4 / 256, 256>>>(x, p_xt, MM * DD / 4);
    conv_tf32_kernel<<<DD * DD / 4 / 256, 256>>>(Wq, p_wq, DD * DD / 4);
    conv_tf32_kernel<<<DD * DD / 4 / 256, 256>>>(Wk, p_wk, DD * DD / 4);
    conv_tf32_kernel<<<DD * DD / 4 / 256, 256>>>(Wv, p_wv, DD * DD / 4);
    conv_tf32_kernel<<<DD * DD / 4 / 256, 256>>>(Wo, p_wo, DD * DD / 4);

    dim3 gproj(DD / 128, MM / 128, 3);   // 8 x 32 x 3
    qkv_gemm_kernel<<<gproj, 256, G_SMEM_BYTES>>>();

    dim3 gattn(SS / 64, BB * HH);        // 32 x 32
    flash_attn_kernel<<<gattn, 256, ATT_SMEM_BYTES>>>();

    dim3 gout(DD / 128, MM / 128);       // 8 x 32
    out_gemm_kernel<<<gout, 256, G_SMEM_BYTES>>>(out);
}

// round 10
// speedup vs baseline: 4.7208x; 2.9532x over previous
#include <cuda_runtime.h>
#include <cuda_fp16.h>
#include <mma.h>
#include <cstdint>

using namespace nvcuda;
namespace wm = nvcuda::wmma;

// Problem constants
#define BB   2
#define SS   2048
#define DD   1024
#define HH   16
#define DHH  64
#define MM   (BB*SS)      // 4096

// -------- scratch (device globals; allocation-free) --------
__device__ __half g_q[MM * DD];
__device__ __half g_k[MM * DD];
__device__ __half g_v[MM * DD];
__device__ __half g_att[MM * DD];
__device__ __half g_xh[MM * DD];
__device__ __half g_wq[DD * DD];
__device__ __half g_wk[DD * DD];
__device__ __half g_wv[DD * DD];
__device__ __half g_wo[DD * DD];

// ---------------- helpers ----------------
__device__ __forceinline__ uint32_t smem_u32(const void* p) {
    uint32_t a;
    asm("{ .reg .u64 t; cvta.to.shared.u64 t, %1; cvt.u32.u64 %0, t; }"
        : "=r"(a) : "l"(p));
    return a;
}
#define CP_ASYNC16(dst_u32, src_ptr) \
    asm volatile("cp.async.cg.shared.global [%0], [%1], 16;" \
                 :: "r"(dst_u32), "l"(src_ptr) : "memory")
#define CP_COMMIT() asm volatile("cp.async.commit_group;" ::: "memory")
#define CP_WAIT1()  asm volatile("cp.async.wait_group 1;" ::: "memory")
#define CP_WAIT0()  asm volatile("cp.async.wait_group 0;" ::: "memory")

extern __shared__ __align__(1024) char dynsm[];

// ============================================================
// float -> half conversion (one-shot)
// ============================================================
__global__ __launch_bounds__(256) void conv_h_kernel(
    const float* __restrict__ src, __half* __restrict__ dst, int n4)
{
    int i = blockIdx.x * blockDim.x + threadIdx.x;
    if (i < n4) {
        float4 v = ((const float4*)src)[i];
        __half2 h0 = __floats2half2_rn(v.x, v.y);
        __half2 h1 = __floats2half2_rn(v.z, v.w);
        uint2 u;
        u.x = *(uint32_t*)&h0;
        u.y = *(uint32_t*)&h1;
        ((uint2*)dst)[i] = u;
    }
}

// ============================================================
// FP16 WMMA GEMM NT with cp.async double buffering.
// C[m,n] = sum_k A[m,k] * B[n,k]; A,B half, accum fp32.
// Block 128x128, k-tile 64 halves, 256 threads, warp tile 32x64.
// ============================================================
#define HPAD 72                        // smem pitch (halves), row = 144 B
#define G_STAGE_H (128 * HPAD)         // halves per operand per stage (9216)
#define G_STAGE_B (G_STAGE_H * 2)      // 18432 B
#define G_NT (DD / 64)                 // 16 k-tiles
#define G_SMEM_BYTES (4 * G_STAGE_B)   // 73728 B (>= 128*132*4 epi scratch)

template <bool HALF_OUT, typename OutT>
__device__ __forceinline__ void gemm_body(
    const __half* __restrict__ A, const __half* __restrict__ Bm,
    OutT* __restrict__ C, int N, int K)
{
    const uint32_t sbase = smem_u32(dynsm);
    const __half* smh = (const __half*)dynsm;
    const int tid  = threadIdx.x;
    const int warp = tid >> 5;
    const int wmi  = warp >> 1;
    const int wni  = warp & 1;
    const int bm   = blockIdx.y * 128;
    const int bn   = blockIdx.x * 128;

    // copy coords: 128 rows x 8 chunks(16B=8 halves); 1024 chunks, 4/thread
    const int crow[4] = { (tid + 0)   >> 3, (tid + 256) >> 3,
                          (tid + 512) >> 3, (tid + 768) >> 3 };
    const int c8 = tid & 7;

    auto issue = [&](int kt, int stage) {
        uint32_t as = sbase + (uint32_t)stage * 2 * G_STAGE_B;
        uint32_t bs = as + G_STAGE_B;
#pragma unroll
        for (int p = 0; p < 4; p++) {
            int row = crow[p];
            uint32_t off = (uint32_t)row * 144 + (uint32_t)c8 * 16;
            CP_ASYNC16(as + off, &A[(size_t)(bm + row) * K + kt * 64 + c8 * 8]);
            CP_ASYNC16(bs + off, &Bm[(size_t)(bn + row) * K + kt * 64 + c8 * 8]);
        }
    };

    wm::fragment<wm::accumulator, 16, 16, 16, float> acc[2][4];
#pragma unroll
    for (int i = 0; i < 2; i++)
#pragma unroll
        for (int j = 0; j < 4; j++) wm::fill_fragment(acc[i][j], 0.f);

    issue(0, 0); CP_COMMIT();
    issue(1, 1); CP_COMMIT();

    for (int kt = 0; kt < G_NT; kt++) {
        if (kt < G_NT - 2) { CP_WAIT1(); } else { CP_WAIT0(); }
        __syncthreads();

        const __half* As = smh + (size_t)(kt & 1) * 2 * G_STAGE_H;
        const __half* Bs = As + G_STAGE_H;
#pragma unroll
        for (int ks = 0; ks < 4; ks++) {
            wm::fragment<wm::matrix_a, 16, 16, 16, __half, wm::row_major> af[2];
            wm::fragment<wm::matrix_b, 16, 16, 16, __half, wm::col_major> bf[4];
#pragma unroll
            for (int i = 0; i < 2; i++)
                wm::load_matrix_sync(af[i], &As[(wmi * 32 + i * 16) * HPAD + ks * 16], HPAD);
#pragma unroll
            for (int j = 0; j < 4; j++)
                wm::load_matrix_sync(bf[j], &Bs[(wni * 64 + j * 16) * HPAD + ks * 16], HPAD);
#pragma unroll
            for (int i = 0; i < 2; i++)
#pragma unroll
                for (int j = 0; j < 4; j++)
                    wm::mma_sync(acc[i][j], af[i], bf[j], acc[i][j]);
        }
        __syncthreads();

        if (kt + 2 < G_NT) { issue(kt + 2, kt & 1); CP_COMMIT(); }
    }

    if (HALF_OUT) {
        // stage fp32 accs in smem, convert, coalesced half2 global stores
        __syncthreads();
        float* Cs = (float*)dynsm;   // pitch 132 floats; 128*132*4 = 67584 B
#pragma unroll
        for (int i = 0; i < 2; i++)
#pragma unroll
            for (int j = 0; j < 4; j++)
                wm::store_matrix_sync(&Cs[(wmi * 32 + i * 16) * 132 + wni * 64 + j * 16],
                                      acc[i][j], 132, wm::mem_row_major);
        __syncthreads();
        __half* Ch = (__half*)C;
#pragma unroll
        for (int it = 0; it < 32; it++) {
            int t   = tid + it * 256;       // 0..8191
            int row = t >> 6;
            int c2  = t & 63;
            __half2 hv = __floats2half2_rn(Cs[row * 132 + c2 * 2],
                                           Cs[row * 132 + c2 * 2 + 1]);
            ((__half2*)&Ch[(size_t)(bm + row) * N + bn])[c2] = hv;
        }
    } else {
#pragma unroll
        for (int i = 0; i < 2; i++)
#pragma unroll
            for (int j = 0; j < 4; j++) {
                int row = bm + wmi * 32 + i * 16;
                int col = bn + wni * 64 + j * 16;
                wm::store_matrix_sync((float*)&C[(size_t)row * N + col], acc[i][j],
                                      N, wm::mem_row_major);
            }
    }
}

__global__ __launch_bounds__(256) void qkv_gemm_kernel()
{
    const __half* Bm;
    __half* C;
    if (blockIdx.z == 0)      { Bm = g_wq; C = g_q; }
    else if (blockIdx.z == 1) { Bm = g_wk; C = g_k; }
    else                      { Bm = g_wv; C = g_v; }
    gemm_body<true>(g_xh, Bm, C, DD, DD);
}

__global__ __launch_bounds__(256) void out_gemm_kernel(float* __restrict__ out)
{
    gemm_body<false>(g_att, g_wo, out, DD, DD);
}

// ============================================================
// Flash attention, fp16 wmma, cp.async double-buffered K/V.
// One CTA per (64-row q-tile, b*H+h). 256 threads, 8 warps.
// smem (bytes): Q 9216 | K0/K1/V0/V1 4x9216 | SPf 18432 | SPh 9216 | Os 18432
// ============================================================
#define A_OFF_Q    0u
#define A_OFF_K0   9216u
#define A_OFF_K1   18432u
#define A_OFF_V0   27648u
#define A_OFF_V1   36864u
#define A_OFF_SPF  46080u
#define A_OFF_SPH  64512u
#define A_OFF_OS   73728u
#define ATT_SMEM_BYTES 92160

__global__ __launch_bounds__(256) void flash_attn_kernel()
{
    const uint32_t sbase = smem_u32(dynsm);
    __half* Qs  = (__half*)(dynsm + A_OFF_Q);     // [64][72] halves
    __half* Kbuf[2] = { (__half*)(dynsm + A_OFF_K0), (__half*)(dynsm + A_OFF_K1) };
    __half* Vbuf[2] = { (__half*)(dynsm + A_OFF_V0), (__half*)(dynsm + A_OFF_V1) };
    float*  SPf = (float*)(dynsm + A_OFF_SPF);    // [64][72] floats (scores)
    __half* SPh = (__half*)(dynsm + A_OFF_SPH);   // [64][72] halves (P)
    float*  Os  = (float*)(dynsm + A_OFF_OS);     // [64][72] floats

    const uint32_t kb[2] = { sbase + A_OFF_K0, sbase + A_OFF_K1 };
    const uint32_t vb[2] = { sbase + A_OFF_V0, sbase + A_OFF_V1 };

    const int tid  = threadIdx.x;
    const int warp = tid >> 5;
    const int wmi  = warp >> 1;
    const int wni  = warp & 1;
    const int qt   = blockIdx.x;
    const int bh   = blockIdx.y;
    const int b    = bh >> 4;
    const int h    = bh & 15;

    const __half* Qb = g_q   + (size_t)b * SS * DD + h * DHH;
    const __half* Kb = g_k   + (size_t)b * SS * DD + h * DHH;
    const __half* Vb = g_v   + (size_t)b * SS * DD + h * DHH;
    __half*       Ob = g_att + (size_t)b * SS * DD + h * DHH;

    // copy coords: 64 rows x 8 chunks(16B); 512 chunks, 2/thread
    const int krow[2] = { (tid + 0) >> 3, (tid + 256) >> 3 };
    const int c8 = tid & 7;

    auto issue_kv = [&](int kt, int bsel) {
#pragma unroll
        for (int p = 0; p < 2; p++) {
            int row = krow[p];
            uint32_t off = (uint32_t)row * 144 + (uint32_t)c8 * 16;
            CP_ASYNC16(kb[bsel] + off, &Kb[(size_t)(kt * 64 + row) * DD + c8 * 8]);
            CP_ASYNC16(vb[bsel] + off, &Vb[(size_t)(kt * 64 + row) * DD + c8 * 8]);
        }
    };

    issue_kv(0, 0); CP_COMMIT();

    // Q load (x0.125 exact in half)
    {
        const __half2 sc = __float2half2_rn(0.125f);
#pragma unroll
        for (int p = 0; p < 2; p++) {
            int row = krow[p];
            uint4 raw = *(const uint4*)&Qb[(size_t)(qt * 64 + row) * DD + c8 * 8];
            __half2 h0 = __hmul2(*(__half2*)&raw.x, sc);
            __half2 h1 = __hmul2(*(__half2*)&raw.y, sc);
            __half2 h2 = __hmul2(*(__half2*)&raw.z, sc);
            __half2 h3 = __hmul2(*(__half2*)&raw.w, sc);
            uint4 o;
            o.x = *(uint32_t*)&h0; o.y = *(uint32_t*)&h1;
            o.z = *(uint32_t*)&h2; o.w = *(uint32_t*)&h3;
            *(uint4*)&Qs[row * HPAD + c8 * 8] = o;
        }
        for (int i = tid; i < 64 * HPAD; i += 256) Os[i] = 0.f;
    }

    const int srow = tid >> 2;
    const int scol = (tid & 3) * 16;
    float m_i = -1e30f, l_i = 0.f;

    for (int kt = 0; kt <= qt; kt++) {
        const int bsel = kt & 1;
        if (kt < qt) { issue_kv(kt + 1, bsel ^ 1); CP_COMMIT(); CP_WAIT1(); }
        else         { CP_WAIT0(); }
        __syncthreads();

        const __half* Kt = Kbuf[bsel];
        const __half* Vt = Vbuf[bsel];

        // S = Q @ K^T  (warp tile 16x32, 4 k16 steps)
        {
            wm::fragment<wm::accumulator, 16, 16, 16, float> sacc[2];
            wm::fill_fragment(sacc[0], 0.f);
            wm::fill_fragment(sacc[1], 0.f);
#pragma unroll
            for (int ks = 0; ks < 4; ks++) {
                wm::fragment<wm::matrix_a, 16, 16, 16, __half, wm::row_major> af;
                wm::load_matrix_sync(af, &Qs[(wmi * 16) * HPAD + ks * 16], HPAD);
#pragma unroll
                for (int j = 0; j < 2; j++) {
                    wm::fragment<wm::matrix_b, 16, 16, 16, __half, wm::col_major> bf;
                    wm::load_matrix_sync(bf, &Kt[(wni * 32 + j * 16) * HPAD + ks * 16], HPAD);
                    wm::mma_sync(sacc[j], af, bf, sacc[j]);
                }
            }
#pragma unroll
            for (int j = 0; j < 2; j++)
                wm::store_matrix_sync(&SPf[(wmi * 16) * HPAD + wni * 32 + j * 16],
                                      sacc[j], HPAD, wm::mem_row_major);
        }
        __syncthreads();

        // Online softmax: 4 lanes per row, 16 cols each
        {
            float s[16];
#pragma unroll
            for (int j = 0; j < 16; j++) s[j] = SPf[srow * HPAD + scol + j];
            if (kt == qt) {
#pragma unroll
                for (int j = 0; j < 16; j++)
                    if (scol + j > srow) s[j] = -1e30f;
            }
            float rm = s[0];
#pragma unroll
            for (int j = 1; j < 16; j++) rm = fmaxf(rm, s[j]);
            rm = fmaxf(rm, __shfl_xor_sync(0xffffffffu, rm, 1));
            rm = fmaxf(rm, __shfl_xor_sync(0xffffffffu, rm, 2));
            float mn  = fmaxf(m_i, rm);
            float fac = __expf(m_i - mn);
            float rs  = 0.f;
#pragma unroll
            for (int j = 0; j < 16; j++) {
                s[j] = __expf(s[j] - mn);
                rs += s[j];
            }
            rs += __shfl_xor_sync(0xffffffffu, rs, 1);
            rs += __shfl_xor_sync(0xffffffffu, rs, 2);
            l_i = l_i * fac + rs;
            m_i = mn;
#pragma unroll
            for (int j = 0; j < 16; j += 4) {
                float4 ov = *(float4*)&Os[srow * HPAD + scol + j];
                ov.x *= fac; ov.y *= fac; ov.z *= fac; ov.w *= fac;
                *(float4*)&Os[srow * HPAD + scol + j] = ov;
            }
#pragma unroll
            for (int j = 0; j < 16; j += 2) {
                __half2 hv = __floats2half2_rn(s[j], s[j + 1]);
                *(__half2*)&SPh[srow * HPAD + scol + j] = hv;
            }
        }
        __syncthreads();

        // O += P @ V  (warp tile 16x32, 4 k16 steps)
        {
            wm::fragment<wm::accumulator, 16, 16, 16, float> oacc[2];
#pragma unroll
            for (int j = 0; j < 2; j++)
                wm::load_matrix_sync(oacc[j], &Os[(wmi * 16) * HPAD + wni * 32 + j * 16],
                                     HPAD, wm::mem_row_major);
#pragma unroll
            for (int ks = 0; ks < 4; ks++) {
                wm::fragment<wm::matrix_a, 16, 16, 16, __half, wm::row_major> af;
                wm::load_matrix_sync(af, &SPh[(wmi * 16) * HPAD + ks * 16], HPAD);
#pragma unroll
                for (int j = 0; j < 2; j++) {
                    wm::fragment<wm::matrix_b, 16, 16, 16, __half, wm::row_major> bf;
                    wm::load_matrix_sync(bf, &Vt[(ks * 16) * HPAD + wni * 32 + j * 16], HPAD);
                    wm::mma_sync(oacc[j], af, bf, oacc[j]);
                }
            }
#pragma unroll
            for (int j = 0; j < 2; j++)
                wm::store_matrix_sync(&Os[(wmi * 16) * HPAD + wni * 32 + j * 16],
                                      oacc[j], HPAD, wm::mem_row_major);
        }
        __syncthreads();   // protects K/V buffers for next iter's issue
    }

    // Finalize: divide by l, write half to g_att
    {
        float inv = 1.0f / l_i;
        int grow = qt * 64 + srow;
#pragma unroll
        for (int j = 0; j < 16; j += 2) {
            float a = Os[srow * HPAD + scol + j]     * inv;
            float c = Os[srow * HPAD + scol + j + 1] * inv;
            __half2 hv = __floats2half2_rn(a, c);
            *(__half2*)&Ob[(size_t)grow * DD + scol + j] = hv;
        }
    }
}

// ============================================================
extern "C" void kernel_launch(void* const* d_in, const int* in_sizes, int n_in,
                              void* d_out, int out_size)
{
    const float* x  = (const float*)d_in[0];
    const float* Wq = (const float*)d_in[1];
    const float* Wk = (const float*)d_in[2];
    const float* Wv = (const float*)d_in[3];
    const float* Wo = (const float*)d_in[4];
    float* out = (float*)d_out;

    cudaFuncSetAttribute(qkv_gemm_kernel,
                         cudaFuncAttributeMaxDynamicSharedMemorySize, G_SMEM_BYTES);
    cudaFuncSetAttribute(out_gemm_kernel,
                         cudaFuncAttributeMaxDynamicSharedMemorySize, G_SMEM_BYTES);
    cudaFuncSetAttribute(flash_attn_kernel,
                         cudaFuncAttributeMaxDynamicSharedMemorySize, ATT_SMEM_BYTES);

    __half *p_xh, *p_wq, *p_wk, *p_wv, *p_wo;
    cudaGetSymbolAddress((void**)&p_xh, g_xh);
    cudaGetSymbolAddress((void**)&p_wq, g_wq);
    cudaGetSymbolAddress((void**)&p_wk, g_wk);
    cudaGetSymbolAddress((void**)&p_wv, g_wv);
    cudaGetSymbolAddress((void**)&p_wo, g_wo);

    conv_h_kernel<<<MM * DD / 4 / 256, 256>>>(x, p_xh, MM * DD / 4);
    conv_h_kernel<<<DD * DD / 4 / 256, 256>>>(Wq, p_wq, DD * DD / 4);
    conv_h_kernel<<<DD * DD / 4 / 256, 256>>>(Wk, p_wk, DD * DD / 4);
    conv_h_kernel<<<DD * DD / 4 / 256, 256>>>(Wv, p_wv, DD * DD / 4);
    conv_h_kernel<<<DD * DD / 4 / 256, 256>>>(Wo, p_wo, DD * DD / 4);

    dim3 gproj(DD / 128, MM / 128, 3);   // 8 x 32 x 3
    qkv_gemm_kernel<<<gproj, 256, G_SMEM_BYTES>>>();

    dim3 gattn(SS / 64, BB * HH);        // 32 x 32
    flash_attn_kernel<<<gattn, 256, ATT_SMEM_BYTES>>>();

    dim3 gout(DD / 128, MM / 128);       // 8 x 32
    out_gemm_kernel<<<gout, 256, G_SMEM_BYTES>>>(out);
}

// round 11
// speedup vs baseline: 6.9768x; 1.4779x over previous
#include <cuda_runtime.h>
#include <cuda_fp16.h>
#include <mma.h>
#include <cstdint>

using namespace nvcuda;
namespace wm = nvcuda::wmma;

// Problem constants
#define BB   2
#define SS   2048
#define DD   1024
#define HH   16
#define DHH  64
#define MM   (BB*SS)      // 4096

// -------- scratch (device globals; allocation-free) --------
__device__ __half g_q[MM * DD];
__device__ __half g_k[MM * DD];
__device__ __half g_v[MM * DD];
__device__ __half g_att[MM * DD];
__device__ __half g_xh[MM * DD];
__device__ __half g_wq[DD * DD];
__device__ __half g_wk[DD * DD];
__device__ __half g_wv[DD * DD];
__device__ __half g_wo[DD * DD];

// ---------------- helpers ----------------
__device__ __forceinline__ uint32_t smem_u32(const void* p) {
    uint32_t a;
    asm("{ .reg .u64 t; cvta.to.shared.u64 t, %1; cvt.u32.u64 %0, t; }"
        : "=r"(a) : "l"(p));
    return a;
}
#define CP_ASYNC16(dst_u32, src_ptr) \
    asm volatile("cp.async.cg.shared.global [%0], [%1], 16;" \
                 :: "r"(dst_u32), "l"(src_ptr) : "memory")
#define CP_COMMIT() asm volatile("cp.async.commit_group;" ::: "memory")
#define CP_WAIT1()  asm volatile("cp.async.wait_group 1;" ::: "memory")
#define CP_WAIT0()  asm volatile("cp.async.wait_group 0;" ::: "memory")

#define LDSM_X4(r0, r1, r2, r3, addr) \
    asm volatile("ldmatrix.sync.aligned.m8n8.x4.shared.b16 {%0,%1,%2,%3}, [%4];" \
                 : "=r"(r0), "=r"(r1), "=r"(r2), "=r"(r3) : "r"(addr))
#define LDSM_X4_T(r0, r1, r2, r3, addr) \
    asm volatile("ldmatrix.sync.aligned.m8n8.x4.trans.shared.b16 {%0,%1,%2,%3}, [%4];" \
                 : "=r"(r0), "=r"(r1), "=r"(r2), "=r"(r3) : "r"(addr))
#define MMA16816(c, a0, a1, a2, a3, b0, b1) \
    asm volatile("mma.sync.aligned.m16n8k16.row.col.f32.f16.f16.f32 " \
                 "{%0,%1,%2,%3}, {%4,%5,%6,%7}, {%8,%9}, {%0,%1,%2,%3};" \
                 : "+f"((c)[0]), "+f"((c)[1]), "+f"((c)[2]), "+f"((c)[3]) \
                 : "r"(a0), "r"(a1), "r"(a2), "r"(a3), "r"(b0), "r"(b1))

__device__ __forceinline__ uint32_t pack_h2(float a, float b) {
    __half2 h = __floats2half2_rn(a, b);
    return *(uint32_t*)&h;
}

extern __shared__ __align__(1024) char dynsm[];

// ============================================================
// float -> half conversions (one-shot)
// ============================================================
__global__ __launch_bounds__(256) void conv_h_kernel(
    const float* __restrict__ src, __half* __restrict__ dst, int n4)
{
    int i = blockIdx.x * blockDim.x + threadIdx.x;
    if (i < n4) {
        float4 v = ((const float4*)src)[i];
        __half2 h0 = __floats2half2_rn(v.x, v.y);
        __half2 h1 = __floats2half2_rn(v.z, v.w);
        uint2 u;
        u.x = *(uint32_t*)&h0;
        u.y = *(uint32_t*)&h1;
        ((uint2*)dst)[i] = u;
    }
}

__global__ __launch_bounds__(256) void conv_w4_kernel(
    const float* __restrict__ w0, const float* __restrict__ w1,
    const float* __restrict__ w2, const float* __restrict__ w3,
    __half* __restrict__ d0, __half* __restrict__ d1,
    __half* __restrict__ d2, __half* __restrict__ d3, int n4)
{
    const float* src = (blockIdx.y == 0) ? w0 : (blockIdx.y == 1) ? w1
                       : (blockIdx.y == 2) ? w2 : w3;
    __half* dst = (blockIdx.y == 0) ? d0 : (blockIdx.y == 1) ? d1
                  : (blockIdx.y == 2) ? d2 : d3;
    int i = blockIdx.x * blockDim.x + threadIdx.x;
    if (i < n4) {
        float4 v = ((const float4*)src)[i];
        __half2 h0 = __floats2half2_rn(v.x, v.y);
        __half2 h1 = __floats2half2_rn(v.z, v.w);
        uint2 u;
        u.x = *(uint32_t*)&h0;
        u.y = *(uint32_t*)&h1;
        ((uint2*)dst)[i] = u;
    }
}

// ============================================================
// FP16 WMMA GEMM NT with cp.async double buffering (R10, passing).
// ============================================================
#define HPAD 72
#define G_STAGE_H (128 * HPAD)
#define G_STAGE_B (G_STAGE_H * 2)
#define G_NT (DD / 64)
#define G_SMEM_BYTES (4 * G_STAGE_B)   // 73728 B

template <bool HALF_OUT, typename OutT>
__device__ __forceinline__ void gemm_body(
    const __half* __restrict__ A, const __half* __restrict__ Bm,
    OutT* __restrict__ C, int N, int K)
{
    const uint32_t sbase = smem_u32(dynsm);
    const __half* smh = (const __half*)dynsm;
    const int tid  = threadIdx.x;
    const int warp = tid >> 5;
    const int wmi  = warp >> 1;
    const int wni  = warp & 1;
    const int bm   = blockIdx.y * 128;
    const int bn   = blockIdx.x * 128;

    const int crow[4] = { (tid + 0)   >> 3, (tid + 256) >> 3,
                          (tid + 512) >> 3, (tid + 768) >> 3 };
    const int c8 = tid & 7;

    auto issue = [&](int kt, int stage) {
        uint32_t as = sbase + (uint32_t)stage * 2 * G_STAGE_B;
        uint32_t bs = as + G_STAGE_B;
#pragma unroll
        for (int p = 0; p < 4; p++) {
            int row = crow[p];
            uint32_t off = (uint32_t)row * 144 + (uint32_t)c8 * 16;
            CP_ASYNC16(as + off, &A[(size_t)(bm + row) * K + kt * 64 + c8 * 8]);
            CP_ASYNC16(bs + off, &Bm[(size_t)(bn + row) * K + kt * 64 + c8 * 8]);
        }
    };

    wm::fragment<wm::accumulator, 16, 16, 16, float> acc[2][4];
#pragma unroll
    for (int i = 0; i < 2; i++)
#pragma unroll
        for (int j = 0; j < 4; j++) wm::fill_fragment(acc[i][j], 0.f);

    issue(0, 0); CP_COMMIT();
    issue(1, 1); CP_COMMIT();

    for (int kt = 0; kt < G_NT; kt++) {
        if (kt < G_NT - 2) { CP_WAIT1(); } else { CP_WAIT0(); }
        __syncthreads();

        const __half* As = smh + (size_t)(kt & 1) * 2 * G_STAGE_H;
        const __half* Bs = As + G_STAGE_H;
#pragma unroll
        for (int ks = 0; ks < 4; ks++) {
            wm::fragment<wm::matrix_a, 16, 16, 16, __half, wm::row_major> af[2];
            wm::fragment<wm::matrix_b, 16, 16, 16, __half, wm::col_major> bf[4];
#pragma unroll
            for (int i = 0; i < 2; i++)
                wm::load_matrix_sync(af[i], &As[(wmi * 32 + i * 16) * HPAD + ks * 16], HPAD);
#pragma unroll
            for (int j = 0; j < 4; j++)
                wm::load_matrix_sync(bf[j], &Bs[(wni * 64 + j * 16) * HPAD + ks * 16], HPAD);
#pragma unroll
            for (int i = 0; i < 2; i++)
#pragma unroll
                for (int j = 0; j < 4; j++)
                    wm::mma_sync(acc[i][j], af[i], bf[j], acc[i][j]);
        }
        __syncthreads();

        if (kt + 2 < G_NT) { issue(kt + 2, kt & 1); CP_COMMIT(); }
    }

    if (HALF_OUT) {
        __syncthreads();
        float* Cs = (float*)dynsm;
#pragma unroll
        for (int i = 0; i < 2; i++)
#pragma unroll
            for (int j = 0; j < 4; j++)
                wm::store_matrix_sync(&Cs[(wmi * 32 + i * 16) * 132 + wni * 64 + j * 16],
                                      acc[i][j], 132, wm::mem_row_major);
        __syncthreads();
        __half* Ch = (__half*)C;
#pragma unroll
        for (int it = 0; it < 32; it++) {
            int t   = tid + it * 256;
            int row = t >> 6;
            int c2  = t & 63;
            __half2 hv = __floats2half2_rn(Cs[row * 132 + c2 * 2],
                                           Cs[row * 132 + c2 * 2 + 1]);
            ((__half2*)&Ch[(size_t)(bm + row) * N + bn])[c2] = hv;
        }
    } else {
#pragma unroll
        for (int i = 0; i < 2; i++)
#pragma unroll
            for (int j = 0; j < 4; j++) {
                int row = bm + wmi * 32 + i * 16;
                int col = bn + wni * 64 + j * 16;
                wm::store_matrix_sync((float*)&C[(size_t)row * N + col], acc[i][j],
                                      N, wm::mem_row_major);
            }
    }
}

__global__ __launch_bounds__(256) void qkv_gemm_kernel()
{
    const __half* Bm;
    __half* C;
    if (blockIdx.z == 0)      { Bm = g_wq; C = g_q; }
    else if (blockIdx.z == 1) { Bm = g_wk; C = g_k; }
    else                      { Bm = g_wv; C = g_v; }
    gemm_body<true>(g_xh, Bm, C, DD, DD);
}

__global__ __launch_bounds__(256) void out_gemm_kernel(float* __restrict__ out)
{
    gemm_body<false>(g_att, g_wo, out, DD, DD);
}

// ============================================================
// Flash attention v2, mma.sync m16n8k16, register-resident S/O.
// CTA: 128 Q rows; 8 warps x 16 rows. K/V 64-token tiles, 3-slot
// cp.async ring, one __syncthreads per k-tile.
// smem: Q 18432 | K ring 3x9216 | V ring 3x9216 = 73728 B.
// ============================================================
#define AQ_OFF  0u
#define AK_OFF  18432u
#define AV_OFF  46080u
#define ATT_SMEM_BYTES 73728

__global__ __launch_bounds__(256) void flash_attn_kernel()
{
    const uint32_t sbase = smem_u32(dynsm);
    const int tid  = threadIdx.x;
    const int warp = tid >> 5;
    const int lane = tid & 31;
    const int qt   = (gridDim.x - 1) - blockIdx.x;   // heavy CTAs first
    const int bh   = blockIdx.y;
    const int b    = bh >> 4;
    const int h    = bh & 15;

    const __half* Qb = g_q   + (size_t)b * SS * DD + h * DHH;
    const __half* Kb = g_k   + (size_t)b * SS * DD + h * DHH;
    const __half* Vb = g_v   + (size_t)b * SS * DD + h * DHH;
    __half*       Ob = g_att + (size_t)b * SS * DD + h * DHH;

    const int ktmax = 2 * qt + 1;        // last kv tile index (inclusive)

    // ---- async copies ----
    const int krow = tid >> 3;           // 0..31
    const int c8   = tid & 7;

    auto issue_kv = [&](int kt, int s) {
        uint32_t kdst = sbase + AK_OFF + (uint32_t)s * 9216;
        uint32_t vdst = sbase + AV_OFF + (uint32_t)s * 9216;
#pragma unroll
        for (int p = 0; p < 2; p++) {
            int row = krow + p * 32;
            uint32_t off = (uint32_t)row * 144 + (uint32_t)c8 * 16;
            CP_ASYNC16(kdst + off, &Kb[(size_t)(kt * 64 + row) * DD + c8 * 8]);
            CP_ASYNC16(vdst + off, &Vb[(size_t)(kt * 64 + row) * DD + c8 * 8]);
        }
    };

    // Q tile (128x64) via cp.async; joins group 0
#pragma unroll
    for (int p = 0; p < 4; p++) {
        int row = krow + p * 32;
        uint32_t off = (uint32_t)row * 144 + (uint32_t)c8 * 16;
        CP_ASYNC16(sbase + AQ_OFF + off,
                   &Qb[(size_t)(qt * 128 + row) * DD + c8 * 8]);
    }
    issue_kv(0, 0); CP_COMMIT();
    if (ktmax >= 1) { issue_kv(1, 1); CP_COMMIT(); }

    // ---- per-warp state ----
    const int g   = lane >> 3;           // ldmatrix address group
    const int lr8 = lane & 7;

    float oacc[8][4];
#pragma unroll
    for (int t = 0; t < 8; t++)
#pragma unroll
        for (int e = 0; e < 4; e++) oacc[t][e] = 0.f;

    float m0 = -1e30f, m1 = -1e30f, l0 = 0.f, l1 = 0.f;

    const int rwbase = qt * 128 + warp * 16;          // warp's first Q row
    const int r0g = rwbase + (lane >> 2);             // thread rows (global)
    const int r1g = r0g + 8;

    uint32_t qa[4][4];
    bool q_loaded = false;

    for (int kt = 0; kt <= ktmax; kt++) {
        if (kt < ktmax) { CP_WAIT1(); } else { CP_WAIT0(); }
        __syncthreads();
        if (kt + 2 <= ktmax) { issue_kv(kt + 2, (kt + 2) % 3); CP_COMMIT(); }

        if (!q_loaded) {   // Q A-fragments, loaded once (after group-0 wait)
#pragma unroll
            for (int ks = 0; ks < 4; ks++) {
                uint32_t addr = sbase + AQ_OFF
                    + (uint32_t)(warp * 16 + lr8 + (g & 1) * 8) * 144
                    + (uint32_t)(ks * 16 + (g >> 1) * 8) * 2;
                LDSM_X4(qa[ks][0], qa[ks][1], qa[ks][2], qa[ks][3], addr);
            }
            q_loaded = true;
        }

        const int slot = kt % 3;
        const uint32_t kbase = sbase + AK_OFF + (uint32_t)slot * 9216;
        const uint32_t vbase = sbase + AV_OFF + (uint32_t)slot * 9216;

        // ---- S = Q @ K^T : 8 n8-tiles, regs only ----
        float sacc[8][4];
#pragma unroll
        for (int t = 0; t < 8; t++)
#pragma unroll
            for (int e = 0; e < 4; e++) sacc[t][e] = 0.f;

#pragma unroll
        for (int ks = 0; ks < 4; ks++) {
#pragma unroll
            for (int nt2 = 0; nt2 < 4; nt2++) {
                uint32_t addr = kbase
                    + (uint32_t)(nt2 * 16 + lr8 + (g >> 1) * 8) * 144
                    + (uint32_t)(ks * 16 + (g & 1) * 8) * 2;
                uint32_t b0, b1, b2, b3;
                LDSM_X4(b0, b1, b2, b3, addr);
                MMA16816(sacc[nt2 * 2 + 0], qa[ks][0], qa[ks][1], qa[ks][2], qa[ks][3], b0, b1);
                MMA16816(sacc[nt2 * 2 + 1], qa[ks][0], qa[ks][1], qa[ks][2], qa[ks][3], b2, b3);
            }
        }

        // ---- online softmax on registers ----
        const bool need_mask = (kt * 64 + 63) > rwbase;
        float vx0 = -1e30f, vx1 = -1e30f;
#pragma unroll
        for (int t = 0; t < 8; t++) {
            float s0 = sacc[t][0] * 0.125f;
            float s1 = sacc[t][1] * 0.125f;
            float s2 = sacc[t][2] * 0.125f;
            float s3 = sacc[t][3] * 0.125f;
            if (need_mask) {
                int c0 = kt * 64 + t * 8 + (lane & 3) * 2;
                if (c0     > r0g) s0 = -1e30f;
                if (c0 + 1 > r0g) s1 = -1e30f;
                if (c0     > r1g) s2 = -1e30f;
                if (c0 + 1 > r1g) s3 = -1e30f;
            }
            sacc[t][0] = s0; sacc[t][1] = s1;
            sacc[t][2] = s2; sacc[t][3] = s3;
            vx0 = fmaxf(vx0, fmaxf(s0, s1));
            vx1 = fmaxf(vx1, fmaxf(s2, s3));
        }
        vx0 = fmaxf(vx0, __shfl_xor_sync(0xffffffffu, vx0, 1));
        vx0 = fmaxf(vx0, __shfl_xor_sync(0xffffffffu, vx0, 2));
        vx1 = fmaxf(vx1, __shfl_xor_sync(0xffffffffu, vx1, 1));
        vx1 = fmaxf(vx1, __shfl_xor_sync(0xffffffffu, vx1, 2));

        float mn0 = fmaxf(m0, vx0);
        float mn1 = fmaxf(m1, vx1);
        float fac0 = __expf(m0 - mn0);
        float fac1 = __expf(m1 - mn1);
        float rs0 = 0.f, rs1 = 0.f;
#pragma unroll
        for (int t = 0; t < 8; t++) {
            float p0 = __expf(sacc[t][0] - mn0);
            float p1 = __expf(sacc[t][1] - mn0);
            float p2 = __expf(sacc[t][2] - mn1);
            float p3 = __expf(sacc[t][3] - mn1);
            sacc[t][0] = p0; sacc[t][1] = p1;
            sacc[t][2] = p2; sacc[t][3] = p3;
            rs0 += p0 + p1;
            rs1 += p2 + p3;
        }
        rs0 += __shfl_xor_sync(0xffffffffu, rs0, 1);
        rs0 += __shfl_xor_sync(0xffffffffu, rs0, 2);
        rs1 += __shfl_xor_sync(0xffffffffu, rs1, 1);
        rs1 += __shfl_xor_sync(0xffffffffu, rs1, 2);
        l0 = l0 * fac0 + rs0;
        l1 = l1 * fac1 + rs1;
        m0 = mn0;
        m1 = mn1;

        // rescale O (c0,c1 -> row r0; c2,c3 -> row r1)
#pragma unroll
        for (int t = 0; t < 8; t++) {
            oacc[t][0] *= fac0; oacc[t][1] *= fac0;
            oacc[t][2] *= fac1; oacc[t][3] *= fac1;
        }

        // ---- O += P @ V : P regs reinterpreted as A fragments ----
#pragma unroll
        for (int ks = 0; ks < 4; ks++) {
            uint32_t pa0 = pack_h2(sacc[2 * ks][0],     sacc[2 * ks][1]);
            uint32_t pa1 = pack_h2(sacc[2 * ks][2],     sacc[2 * ks][3]);
            uint32_t pa2 = pack_h2(sacc[2 * ks + 1][0], sacc[2 * ks + 1][1]);
            uint32_t pa3 = pack_h2(sacc[2 * ks + 1][2], sacc[2 * ks + 1][3]);
#pragma unroll
            for (int nt2 = 0; nt2 < 4; nt2++) {
                uint32_t addr = vbase
                    + (uint32_t)(ks * 16 + lr8 + (g & 1) * 8) * 144
                    + (uint32_t)(nt2 * 16 + (g >> 1) * 8) * 2;
                uint32_t b0, b1, b2, b3;
                LDSM_X4_T(b0, b1, b2, b3, addr);
                MMA16816(oacc[nt2 * 2 + 0], pa0, pa1, pa2, pa3, b0, b1);
                MMA16816(oacc[nt2 * 2 + 1], pa0, pa1, pa2, pa3, b2, b3);
            }
        }
    }

    // ---- finalize ----
    float inv0 = 1.0f / l0;
    float inv1 = 1.0f / l1;
#pragma unroll
    for (int t = 0; t < 8; t++) {
        int col = t * 8 + (lane & 3) * 2;
        __half2 h0 = __floats2half2_rn(oacc[t][0] * inv0, oacc[t][1] * inv0);
        __half2 h1 = __floats2half2_rn(oacc[t][2] * inv1, oacc[t][3] * inv1);
        *(__half2*)&Ob[(size_t)r0g * DD + col] = h0;
        *(__half2*)&Ob[(size_t)r1g * DD + col] = h1;
    }
}

// ============================================================
extern "C" void kernel_launch(void* const* d_in, const int* in_sizes, int n_in,
                              void* d_out, int out_size)
{
    const float* x  = (const float*)d_in[0];
    const float* Wq = (const float*)d_in[1];
    const float* Wk = (const float*)d_in[2];
    const float* Wv = (const float*)d_in[3];
    const float* Wo = (const float*)d_in[4];
    float* out = (float*)d_out;

    cudaFuncSetAttribute(qkv_gemm_kernel,
                         cudaFuncAttributeMaxDynamicSharedMemorySize, G_SMEM_BYTES);
    cudaFuncSetAttribute(out_gemm_kernel,
                         cudaFuncAttributeMaxDynamicSharedMemorySize, G_SMEM_BYTES);
    cudaFuncSetAttribute(flash_attn_kernel,
                         cudaFuncAttributeMaxDynamicSharedMemorySize, ATT_SMEM_BYTES);

    __half *p_xh, *p_wq, *p_wk, *p_wv, *p_wo;
    cudaGetSymbolAddress((void**)&p_xh, g_xh);
    cudaGetSymbolAddress((void**)&p_wq, g_wq);
    cudaGetSymbolAddress((void**)&p_wk, g_wk);
    cudaGetSymbolAddress((void**)&p_wv, g_wv);
    cudaGetSymbolAddress((void**)&p_wo, g_wo);

    conv_h_kernel<<<MM * DD / 4 / 256, 256>>>(x, p_xh, MM * DD / 4);
    dim3 gw(DD * DD / 4 / 256, 4);
    conv_w4_kernel<<<gw, 256>>>(Wq, Wk, Wv, Wo, p_wq, p_wk, p_wv, p_wo,
                                DD * DD / 4);

    dim3 gproj(DD / 128, MM / 128, 3);   // 8 x 32 x 3
    qkv_gemm_kernel<<<gproj, 256, G_SMEM_BYTES>>>();

    dim3 gattn(SS / 128, BB * HH);       // 16 x 32
    flash_attn_kernel<<<gattn, 256, ATT_SMEM_BYTES>>>();

    dim3 gout(DD / 128, MM / 128);       // 8 x 32
    out_gemm_kernel<<<gout, 256, G_SMEM_BYTES>>>(out);
}

// round 12
// speedup vs baseline: 7.5027x; 1.0754x over previous
#include <cuda_runtime.h>
#include <cuda_fp16.h>
#include <mma.h>
#include <cstdint>

using namespace nvcuda;
namespace wm = nvcuda::wmma;

// Problem constants
#define BB   2
#define SS   2048
#define DD   1024
#define HH   16
#define DHH  64
#define MM   (BB*SS)      // 4096

// softmax scale folded into Q: 0.125 * log2(e)
#define QSCALE 0.18033688011112042f

// -------- scratch (device globals; allocation-free) --------
__device__ __half g_q[MM * DD];
__device__ __half g_k[MM * DD];
__device__ __half g_v[MM * DD];
__device__ __half g_att[MM * DD];
__device__ __half g_xh[MM * DD];
__device__ __half g_wq[DD * DD];
__device__ __half g_wk[DD * DD];
__device__ __half g_wv[DD * DD];
__device__ __half g_wo[DD * DD];

// ---------------- helpers ----------------
__device__ __forceinline__ uint32_t smem_u32(const void* p) {
    uint32_t a;
    asm("{ .reg .u64 t; cvta.to.shared.u64 t, %1; cvt.u32.u64 %0, t; }"
        : "=r"(a) : "l"(p));
    return a;
}
#define CP_ASYNC16(dst_u32, src_ptr) \
    asm volatile("cp.async.cg.shared.global [%0], [%1], 16;" \
                 :: "r"(dst_u32), "l"(src_ptr) : "memory")
#define CP_COMMIT() asm volatile("cp.async.commit_group;" ::: "memory")
#define CP_WAIT1()  asm volatile("cp.async.wait_group 1;" ::: "memory")
#define CP_WAIT0()  asm volatile("cp.async.wait_group 0;" ::: "memory")

#define LDSM_X4(r0, r1, r2, r3, addr) \
    asm volatile("ldmatrix.sync.aligned.m8n8.x4.shared.b16 {%0,%1,%2,%3}, [%4];" \
                 : "=r"(r0), "=r"(r1), "=r"(r2), "=r"(r3) : "r"(addr))
#define LDSM_X4_T(r0, r1, r2, r3, addr) \
    asm volatile("ldmatrix.sync.aligned.m8n8.x4.trans.shared.b16 {%0,%1,%2,%3}, [%4];" \
                 : "=r"(r0), "=r"(r1), "=r"(r2), "=r"(r3) : "r"(addr))
#define MMA16816(c, a0, a1, a2, a3, b0, b1) \
    asm volatile("mma.sync.aligned.m16n8k16.row.col.f32.f16.f16.f32 " \
                 "{%0,%1,%2,%3}, {%4,%5,%6,%7}, {%8,%9}, {%0,%1,%2,%3};" \
                 : "+f"((c)[0]), "+f"((c)[1]), "+f"((c)[2]), "+f"((c)[3]) \
                 : "r"(a0), "r"(a1), "r"(a2), "r"(a3), "r"(b0), "r"(b1))

__device__ __forceinline__ uint32_t ex2_h2(float a, float b) {
    __half2 d = __floats2half2_rn(a, b);
    uint32_t din = *(uint32_t*)&d, p;
    asm("ex2.approx.f16x2 %0, %1;" : "=r"(p) : "r"(din));
    return p;
}

extern __shared__ __align__(1024) char dynsm[];

// ============================================================
// fused float -> half conversion for all 5 tensors (one launch)
// ============================================================
#define XN4 (MM * DD / 4)          // 1048576
#define WN4 (DD * DD / 4)          // 262144 = 2^18

__global__ __launch_bounds__(256) void conv_all_kernel(
    const float* __restrict__ x,
    const float* __restrict__ wq, const float* __restrict__ wk,
    const float* __restrict__ wv, const float* __restrict__ wo)
{
    int i = blockIdx.x * blockDim.x + threadIdx.x;
    const float* src;
    __half* dst;
    int o;
    if (i < XN4) {
        src = x; dst = g_xh; o = i;
    } else {
        int j = i - XN4;
        int w = j >> 18;
        o = j & (WN4 - 1);
        src = (w == 0) ? wq : (w == 1) ? wk : (w == 2) ? wv : wo;
        dst = (w == 0) ? g_wq : (w == 1) ? g_wk : (w == 2) ? g_wv : g_wo;
    }
    float4 v = ((const float4*)src)[o];
    __half2 h0 = __floats2half2_rn(v.x, v.y);
    __half2 h1 = __floats2half2_rn(v.z, v.w);
    uint2 u;
    u.x = *(uint32_t*)&h0;
    u.y = *(uint32_t*)&h1;
    ((uint2*)dst)[o] = u;
}

// ============================================================
// FP16 WMMA GEMM NT with cp.async double buffering.
// ============================================================
#define HPAD 72
#define G_STAGE_H (128 * HPAD)
#define G_STAGE_B (G_STAGE_H * 2)
#define G_NT (DD / 64)
#define G_SMEM_BYTES (4 * G_STAGE_B)   // 73728 B

template <bool HALF_OUT, typename OutT>
__device__ __forceinline__ void gemm_body(
    const __half* __restrict__ A, const __half* __restrict__ Bm,
    OutT* __restrict__ C, int N, int K, float oscale)
{
    const uint32_t sbase = smem_u32(dynsm);
    const __half* smh = (const __half*)dynsm;
    const int tid  = threadIdx.x;
    const int warp = tid >> 5;
    const int wmi  = warp >> 1;
    const int wni  = warp & 1;
    const int bm   = blockIdx.y * 128;
    const int bn   = blockIdx.x * 128;

    const int crow[4] = { (tid + 0)   >> 3, (tid + 256) >> 3,
                          (tid + 512) >> 3, (tid + 768) >> 3 };
    const int c8 = tid & 7;

    auto issue = [&](int kt, int stage) {
        uint32_t as = sbase + (uint32_t)stage * 2 * G_STAGE_B;
        uint32_t bs = as + G_STAGE_B;
#pragma unroll
        for (int p = 0; p < 4; p++) {
            int row = crow[p];
            uint32_t off = (uint32_t)row * 144 + (uint32_t)c8 * 16;
            CP_ASYNC16(as + off, &A[(size_t)(bm + row) * K + kt * 64 + c8 * 8]);
            CP_ASYNC16(bs + off, &Bm[(size_t)(bn + row) * K + kt * 64 + c8 * 8]);
        }
    };

    wm::fragment<wm::accumulator, 16, 16, 16, float> acc[2][4];
#pragma unroll
    for (int i = 0; i < 2; i++)
#pragma unroll
        for (int j = 0; j < 4; j++) wm::fill_fragment(acc[i][j], 0.f);

    issue(0, 0); CP_COMMIT();
    issue(1, 1); CP_COMMIT();

    for (int kt = 0; kt < G_NT; kt++) {
        if (kt < G_NT - 2) { CP_WAIT1(); } else { CP_WAIT0(); }
        __syncthreads();

        const __half* As = smh + (size_t)(kt & 1) * 2 * G_STAGE_H;
        const __half* Bs = As + G_STAGE_H;
#pragma unroll
        for (int ks = 0; ks < 4; ks++) {
            wm::fragment<wm::matrix_a, 16, 16, 16, __half, wm::row_major> af[2];
            wm::fragment<wm::matrix_b, 16, 16, 16, __half, wm::col_major> bf[4];
#pragma unroll
            for (int i = 0; i < 2; i++)
                wm::load_matrix_sync(af[i], &As[(wmi * 32 + i * 16) * HPAD + ks * 16], HPAD);
#pragma unroll
            for (int j = 0; j < 4; j++)
                wm::load_matrix_sync(bf[j], &Bs[(wni * 64 + j * 16) * HPAD + ks * 16], HPAD);
#pragma unroll
            for (int i = 0; i < 2; i++)
#pragma unroll
                for (int j = 0; j < 4; j++)
                    wm::mma_sync(acc[i][j], af[i], bf[j], acc[i][j]);
        }
        __syncthreads();

        if (kt + 2 < G_NT) { issue(kt + 2, kt & 1); CP_COMMIT(); }
    }

    if (HALF_OUT) {
        __syncthreads();
        float* Cs = (float*)dynsm;
#pragma unroll
        for (int i = 0; i < 2; i++)
#pragma unroll
            for (int j = 0; j < 4; j++)
                wm::store_matrix_sync(&Cs[(wmi * 32 + i * 16) * 132 + wni * 64 + j * 16],
                                      acc[i][j], 132, wm::mem_row_major);
        __syncthreads();
        __half* Ch = (__half*)C;
#pragma unroll
        for (int it = 0; it < 32; it++) {
            int t   = tid + it * 256;
            int row = t >> 6;
            int c2  = t & 63;
            __half2 hv = __floats2half2_rn(Cs[row * 132 + c2 * 2] * oscale,
                                           Cs[row * 132 + c2 * 2 + 1] * oscale);
            ((__half2*)&Ch[(size_t)(bm + row) * N + bn])[c2] = hv;
        }
    } else {
#pragma unroll
        for (int i = 0; i < 2; i++)
#pragma unroll
            for (int j = 0; j < 4; j++) {
                int row = bm + wmi * 32 + i * 16;
                int col = bn + wni * 64 + j * 16;
                wm::store_matrix_sync((float*)&C[(size_t)row * N + col], acc[i][j],
                                      N, wm::mem_row_major);
            }
    }
}

__global__ __launch_bounds__(256) void qkv_gemm_kernel()
{
    const __half* Bm;
    __half* C;
    float sc;
    if (blockIdx.z == 0)      { Bm = g_wq; C = g_q; sc = QSCALE; }
    else if (blockIdx.z == 1) { Bm = g_wk; C = g_k; sc = 1.0f; }
    else                      { Bm = g_wv; C = g_v; sc = 1.0f; }
    gemm_body<true>(g_xh, Bm, C, DD, DD, sc);
}

__global__ __launch_bounds__(256) void out_gemm_kernel(float* __restrict__ out)
{
    gemm_body<false>(g_att, g_wo, out, DD, DD, 1.0f);
}

// ============================================================
// Flash attention v2, mma.sync m16n8k16, register-resident S/O.
// Q pre-scaled by 0.125*log2e -> softmax in exp2 domain with
// ex2.approx.f16x2 (P lands directly in packed fp16 A-fragments).
// CTA: 128 Q rows; 8 warps x 16 rows; 3-slot cp.async K/V ring.
// ============================================================
#define AQ_OFF  0u
#define AK_OFF  18432u
#define AV_OFF  46080u
#define ATT_SMEM_BYTES 73728

__global__ __launch_bounds__(256) void flash_attn_kernel()
{
    const uint32_t sbase = smem_u32(dynsm);
    const int tid  = threadIdx.x;
    const int warp = tid >> 5;
    const int lane = tid & 31;
    const int qt   = (gridDim.x - 1) - blockIdx.x;   // heavy CTAs first
    const int bh   = blockIdx.y;
    const int b    = bh >> 4;
    const int h    = bh & 15;

    const __half* Qb = g_q   + (size_t)b * SS * DD + h * DHH;
    const __half* Kb = g_k   + (size_t)b * SS * DD + h * DHH;
    const __half* Vb = g_v   + (size_t)b * SS * DD + h * DHH;
    __half*       Ob = g_att + (size_t)b * SS * DD + h * DHH;

    const int ktmax = 2 * qt + 1;

    const int krow = tid >> 3;
    const int c8   = tid & 7;

    auto issue_kv = [&](int kt, int s) {
        uint32_t kdst = sbase + AK_OFF + (uint32_t)s * 9216;
        uint32_t vdst = sbase + AV_OFF + (uint32_t)s * 9216;
#pragma unroll
        for (int p = 0; p < 2; p++) {
            int row = krow + p * 32;
            uint32_t off = (uint32_t)row * 144 + (uint32_t)c8 * 16;
            CP_ASYNC16(kdst + off, &Kb[(size_t)(kt * 64 + row) * DD + c8 * 8]);
            CP_ASYNC16(vdst + off, &Vb[(size_t)(kt * 64 + row) * DD + c8 * 8]);
        }
    };

#pragma unroll
    for (int p = 0; p < 4; p++) {
        int row = krow + p * 32;
        uint32_t off = (uint32_t)row * 144 + (uint32_t)c8 * 16;
        CP_ASYNC16(sbase + AQ_OFF + off,
                   &Qb[(size_t)(qt * 128 + row) * DD + c8 * 8]);
    }
    issue_kv(0, 0); CP_COMMIT();
    if (ktmax >= 1) { issue_kv(1, 1); CP_COMMIT(); }

    const int g   = lane >> 3;
    const int lr8 = lane & 7;

    float oacc[8][4];
#pragma unroll
    for (int t = 0; t < 8; t++)
#pragma unroll
        for (int e = 0; e < 4; e++) oacc[t][e] = 0.f;

    float m0 = -1e30f, m1 = -1e30f, l0 = 0.f, l1 = 0.f;

    const int rwbase = qt * 128 + warp * 16;
    const int r0g = rwbase + (lane >> 2);
    const int r1g = r0g + 8;

    uint32_t qa[4][4];
    bool q_loaded = false;

    for (int kt = 0; kt <= ktmax; kt++) {
        if (kt < ktmax) { CP_WAIT1(); } else { CP_WAIT0(); }
        __syncthreads();
        if (kt + 2 <= ktmax) { issue_kv(kt + 2, (kt + 2) % 3); CP_COMMIT(); }

        if (!q_loaded) {
#pragma unroll
            for (int ks = 0; ks < 4; ks++) {
                uint32_t addr = sbase + AQ_OFF
                    + (uint32_t)(warp * 16 + lr8 + (g & 1) * 8) * 144
                    + (uint32_t)(ks * 16 + (g >> 1) * 8) * 2;
                LDSM_X4(qa[ks][0], qa[ks][1], qa[ks][2], qa[ks][3], addr);
            }
            q_loaded = true;
        }

        const int slot = kt % 3;
        const uint32_t kbase = sbase + AK_OFF + (uint32_t)slot * 9216;
        const uint32_t vbase = sbase + AV_OFF + (uint32_t)slot * 9216;

        // ---- S = Q @ K^T (exp2 domain; Q pre-scaled) ----
        float sacc[8][4];
#pragma unroll
        for (int t = 0; t < 8; t++)
#pragma unroll
            for (int e = 0; e < 4; e++) sacc[t][e] = 0.f;

#pragma unroll
        for (int ks = 0; ks < 4; ks++) {
#pragma unroll
            for (int nt2 = 0; nt2 < 4; nt2++) {
                uint32_t addr = kbase
                    + (uint32_t)(nt2 * 16 + lr8 + (g >> 1) * 8) * 144
                    + (uint32_t)(ks * 16 + (g & 1) * 8) * 2;
                uint32_t b0, b1, b2, b3;
                LDSM_X4(b0, b1, b2, b3, addr);
                MMA16816(sacc[nt2 * 2 + 0], qa[ks][0], qa[ks][1], qa[ks][2], qa[ks][3], b0, b1);
                MMA16816(sacc[nt2 * 2 + 1], qa[ks][0], qa[ks][1], qa[ks][2], qa[ks][3], b2, b3);
            }
        }

        // ---- online softmax (exp2 domain, f16x2 exp) ----
        const bool need_mask = (kt * 64 + 63) > rwbase;
        float vx0 = -1e30f, vx1 = -1e30f;
        if (need_mask) {
#pragma unroll
            for (int t = 0; t < 8; t++) {
                int c0 = kt * 64 + t * 8 + (lane & 3) * 2;
                if (c0     > r0g) sacc[t][0] = -1e30f;
                if (c0 + 1 > r0g) sacc[t][1] = -1e30f;
                if (c0     > r1g) sacc[t][2] = -1e30f;
                if (c0 + 1 > r1g) sacc[t][3] = -1e30f;
            }
        }
#pragma unroll
        for (int t = 0; t < 8; t++) {
            vx0 = fmaxf(vx0, fmaxf(sacc[t][0], sacc[t][1]));
            vx1 = fmaxf(vx1, fmaxf(sacc[t][2], sacc[t][3]));
        }
        vx0 = fmaxf(vx0, __shfl_xor_sync(0xffffffffu, vx0, 1));
        vx0 = fmaxf(vx0, __shfl_xor_sync(0xffffffffu, vx0, 2));
        vx1 = fmaxf(vx1, __shfl_xor_sync(0xffffffffu, vx1, 1));
        vx1 = fmaxf(vx1, __shfl_xor_sync(0xffffffffu, vx1, 2));

        float mn0 = fmaxf(m0, vx0);
        float mn1 = fmaxf(m1, vx1);
        float fac0 = exp2f(m0 - mn0);
        float fac1 = exp2f(m1 - mn1);

        uint32_t ph01[8], ph23[8];
        float rs0 = 0.f, rs1 = 0.f;
#pragma unroll
        for (int t = 0; t < 8; t++) {
            uint32_t p01 = ex2_h2(sacc[t][0] - mn0, sacc[t][1] - mn0);
            uint32_t p23 = ex2_h2(sacc[t][2] - mn1, sacc[t][3] - mn1);
            ph01[t] = p01;
            ph23[t] = p23;
            float2 f01 = __half22float2(*(__half2*)&p01);
            float2 f23 = __half22float2(*(__half2*)&p23);
            rs0 += f01.x + f01.y;
            rs1 += f23.x + f23.y;
        }
        rs0 += __shfl_xor_sync(0xffffffffu, rs0, 1);
        rs0 += __shfl_xor_sync(0xffffffffu, rs0, 2);
        rs1 += __shfl_xor_sync(0xffffffffu, rs1, 1);
        rs1 += __shfl_xor_sync(0xffffffffu, rs1, 2);
        l0 = l0 * fac0 + rs0;
        l1 = l1 * fac1 + rs1;
        m0 = mn0;
        m1 = mn1;

#pragma unroll
        for (int t = 0; t < 8; t++) {
            oacc[t][0] *= fac0; oacc[t][1] *= fac0;
            oacc[t][2] *= fac1; oacc[t][3] *= fac1;
        }

        // ---- O += P @ V (P already packed fp16) ----
#pragma unroll
        for (int ks = 0; ks < 4; ks++) {
            uint32_t pa0 = ph01[2 * ks];
            uint32_t pa1 = ph23[2 * ks];
            uint32_t pa2 = ph01[2 * ks + 1];
            uint32_t pa3 = ph23[2 * ks + 1];
#pragma unroll
            for (int nt2 = 0; nt2 < 4; nt2++) {
                uint32_t addr = vbase
                    + (uint32_t)(ks * 16 + lr8 + (g & 1) * 8) * 144
                    + (uint32_t)(nt2 * 16 + (g >> 1) * 8) * 2;
                uint32_t b0, b1, b2, b3;
                LDSM_X4_T(b0, b1, b2, b3, addr);
                MMA16816(oacc[nt2 * 2 + 0], pa0, pa1, pa2, pa3, b0, b1);
                MMA16816(oacc[nt2 * 2 + 1], pa0, pa1, pa2, pa3, b2, b3);
            }
        }
    }

    // ---- finalize ----
    float inv0 = 1.0f / l0;
    float inv1 = 1.0f / l1;
#pragma unroll
    for (int t = 0; t < 8; t++) {
        int col = t * 8 + (lane & 3) * 2;
        __half2 h0 = __floats2half2_rn(oacc[t][0] * inv0, oacc[t][1] * inv0);
        __half2 h1 = __floats2half2_rn(oacc[t][2] * inv1, oacc[t][3] * inv1);
        *(__half2*)&Ob[(size_t)r0g * DD + col] = h0;
        *(__half2*)&Ob[(size_t)r1g * DD + col] = h1;
    }
}

// ============================================================
extern "C" void kernel_launch(void* const* d_in, const int* in_sizes, int n_in,
                              void* d_out, int out_size)
{
    const float* x  = (const float*)d_in[0];
    const float* Wq = (const float*)d_in[1];
    const float* Wk = (const float*)d_in[2];
    const float* Wv = (const float*)d_in[3];
    const float* Wo = (const float*)d_in[4];
    float* out = (float*)d_out;

    cudaFuncSetAttribute(qkv_gemm_kernel,
                         cudaFuncAttributeMaxDynamicSharedMemorySize, G_SMEM_BYTES);
    cudaFuncSetAttribute(out_gemm_kernel,
                         cudaFuncAttributeMaxDynamicSharedMemorySize, G_SMEM_BYTES);
    cudaFuncSetAttribute(flash_attn_kernel,
                         cudaFuncAttributeMaxDynamicSharedMemorySize, ATT_SMEM_BYTES);

    conv_all_kernel<<<(XN4 + 4 * WN4) / 256, 256>>>(x, Wq, Wk, Wv, Wo);

    dim3 gproj(DD / 128, MM / 128, 3);   // 8 x 32 x 3
    qkv_gemm_kernel<<<gproj, 256, G_SMEM_BYTES>>>();

    dim3 gattn(SS / 128, BB * HH);       // 16 x 32
    flash_attn_kernel<<<gattn, 256, ATT_SMEM_BYTES>>>();

    dim3 gout(DD / 128, MM / 128);       // 8 x 32
    out_gemm_kernel<<<gout, 256, G_SMEM_BYTES>>>(out);
}